// round 8
// baseline (speedup 1.0000x reference)
#include <cuda_runtime.h>
#include <cstdint>

#define NB 4
#define NN 4096
#define FF 256
#define HH 256
#define EE 262144
#define NTOT 16384
#define EP (EE + NTOT)
#define LL 3

// ---------------- scratch (static device memory; no allocation) ----------------
__device__ __align__(16) float g_xpad[NB * (NN + 2) * FF];   // padded x (tf32-rounded)
__device__ __align__(16) float g_Wb[768 * 256];              // conv weight [K,N] (tf32-rounded)
__device__ __align__(16) float g_Wl[LL * 256 * 256];         // gat_W rounded copies
__device__ __align__(16) float g_h0[NTOT * HH];
__device__ __align__(16) float g_h1[NTOT * HH];
__device__ __align__(16) float g_hw[NTOT * HH];
__device__ float g_s[NTOT];
__device__ float g_d[NTOT];
__device__ int   g_deg[NTOT];
__device__ int   g_off[NTOT + 1];
__device__ int   g_cur[NTOT];
__device__ int   g_csrc[EP];

__device__ __forceinline__ float cvt_tf32(float x) {
    uint32_t u;
    asm("cvt.rna.tf32.f32 %0, %1;" : "=r"(u) : "f"(x));
    return __uint_as_float(u);
}
__device__ __forceinline__ float4 cvt4_tf32(float4 v) {
    return make_float4(cvt_tf32(v.x), cvt_tf32(v.y), cvt_tf32(v.z), cvt_tf32(v.w));
}

// ---------------- build padded x (tf32-rounded) ----------------
__global__ void k_xpad(const float* __restrict__ x) {
    int idx = blockIdx.x * 256 + threadIdx.x;       // over NB*4098*64 float4s
    if (idx >= NB * 4098 * 64) return;
    int c4 = idx & 63;
    int m  = (idx >> 6) % 4098;
    int b  = idx / (4098 * 64);
    float4 v = make_float4(0.f, 0.f, 0.f, 0.f);
    if (m >= 1 && m <= 4096)
        v = cvt4_tf32(((const float4*)x)[(b * 4096 + (m - 1)) * 64 + c4]);
    ((float4*)g_xpad)[idx] = v;
}

// Wb[(k*256 + c)*256 + o] = tc_w[o][c][k]  (rounded)
__global__ void k_wb(const float* __restrict__ tc_w) {
    int idx = blockIdx.x * 256 + threadIdx.x;       // 768*256
    int o = idx & 255;
    int r = idx >> 8;
    int c = r & 255;
    int k = r >> 8;
    g_Wb[idx] = cvt_tf32(tc_w[o * 768 + c * 3 + k]);
}

// rounded copy of gat_W
__global__ void k_wl(const float* __restrict__ gat_W) {
    int idx = blockIdx.x * 256 + threadIdx.x;       // LL*256*256
    g_Wl[idx] = cvt_tf32(gat_W[idx]);
}

// ---------------- CSR build (by dst, self-loops included); edge_index is int32 ----------------
__global__ void k_deg_init() {
    int i = blockIdx.x * 256 + threadIdx.x;
    if (i < NTOT) g_deg[i] = 1;                     // self loop
}
__global__ void k_deg_count(const int* __restrict__ ei) {
    int e = blockIdx.x * 256 + threadIdx.x;
    if (e < EE) atomicAdd(&g_deg[ei[EE + e]], 1);
}
__global__ void k_scan() {
    __shared__ int ssum[1024];
    int t = threadIdx.x;
    int v[16]; int tot = 0;
#pragma unroll
    for (int i = 0; i < 16; i++) { v[i] = g_deg[t * 16 + i]; tot += v[i]; }
    ssum[t] = tot;
    __syncthreads();
    for (int off = 1; off < 1024; off <<= 1) {
        int xv = (t >= off) ? ssum[t - off] : 0;
        __syncthreads();
        ssum[t] += xv;
        __syncthreads();
    }
    int pre = (t == 0) ? 0 : ssum[t - 1];
#pragma unroll
    for (int i = 0; i < 16; i++) {
        g_off[t * 16 + i] = pre;
        g_cur[t * 16 + i] = pre;
        pre += v[i];
    }
    if (t == 1023) g_off[NTOT] = ssum[1023];
}
__global__ void k_fill(const int* __restrict__ ei) {
    int idx = blockIdx.x * 256 + threadIdx.x;
    if (idx < NTOT) {
        int pos = atomicAdd(&g_cur[idx], 1);
        g_csrc[pos] = idx;                           // self loop
    } else if (idx < NTOT + EE) {
        int e   = idx - NTOT;
        int src = ei[e];
        int dst = ei[EE + e];
        int pos = atomicAdd(&g_cur[dst], 1);
        g_csrc[pos] = src;
    }
}

// ---------------- tf32 MMA GEMM: cp.async 2-stage, 128x128x32, 8 warps ----------------
#define AS_STRIDE 36
#define BS_STRIDE 136
#define AS_BUF (128 * AS_STRIDE)
#define BS_BUF (32 * BS_STRIDE)
#define MMA_SMEM_BYTES ((2 * AS_BUF + 2 * BS_BUF) * 4)   // 71680 B

__device__ __forceinline__ void cp_async16(uint32_t saddr, const void* gptr) {
    asm volatile("cp.async.cg.shared.global [%0], [%1], 16;\n" :: "r"(saddr), "l"(gptr));
}

// LAYER: -1 = conv (A=g_xpad, B=g_Wb, K=768, epilogue), 0..2 = GAT layer
template <int LAYER>
__global__ __launch_bounds__(256, 2)
void k_mma(int flip, const float* __restrict__ bias, const float* __restrict__ resid) {
    constexpr bool CONV = (LAYER < 0);
    const float* A  = CONV ? g_xpad : (flip ? g_h1 : g_h0);
    const float* Bg = CONV ? g_Wb : g_Wl + (LAYER < 0 ? 0 : LAYER) * 65536;
    float* C        = CONV ? g_h0 : g_hw;
    const int T     = CONV ? 24 : 8;

    extern __shared__ __align__(16) float smem[];
    float* Asm = smem;
    float* Bsm = smem + 2 * AS_BUF;
    uint32_t sA = (uint32_t)__cvta_generic_to_shared(Asm);
    uint32_t sB = (uint32_t)__cvta_generic_to_shared(Bsm);

    int tid  = threadIdx.x;
    int wid  = tid >> 5, lane = tid & 31;
    int gid  = lane >> 2, tig = lane & 3;
    int wm   = (wid >> 2) * 64;
    int wn   = (wid & 3) * 32;
    int bm   = blockIdx.y * 128, bn = blockIdx.x * 128;

    int raw = tid >> 3;
    int caw = (tid & 7) * 4;
    int rbw = tid >> 5;
    int cbw = (tid & 31) * 4;

    float acc[4][4][4];
#pragma unroll
    for (int mt = 0; mt < 4; mt++)
#pragma unroll
        for (int nt = 0; nt < 4; nt++)
#pragma unroll
            for (int r = 0; r < 4; r++) acc[mt][nt][r] = 0.f;

#pragma unroll
    for (int i = 0; i < 4; i++) {
        int r = raw + i * 32;
        int row = bm + r;
        const float* ga = A + (CONV ? row * 256 + (row >> 12) * 512 + caw
                                    : row * 256 + caw);
        cp_async16(sA + (r * AS_STRIDE + caw) * 4, ga);
        int rb = rbw + i * 8;
        cp_async16(sB + (rb * BS_STRIDE + cbw) * 4, Bg + rb * 256 + bn + cbw);
    }
    asm volatile("cp.async.commit_group;\n");

    for (int t = 0; t < T; t++) {
        int buf = t & 1;
        if (t + 1 < T) {
            int k0 = (t + 1) * 32;
            uint32_t dA = sA + ((buf ^ 1) * AS_BUF) * 4;
            uint32_t dB = sB + ((buf ^ 1) * BS_BUF) * 4;
#pragma unroll
            for (int i = 0; i < 4; i++) {
                int r = raw + i * 32;
                int row = bm + r;
                const float* ga = A + (CONV ? row * 256 + (row >> 12) * 512 + k0 + caw
                                            : row * 256 + k0 + caw);
                cp_async16(dA + (r * AS_STRIDE + caw) * 4, ga);
                int rb = rbw + i * 8;
                cp_async16(dB + (rb * BS_STRIDE + cbw) * 4, Bg + (k0 + rb) * 256 + bn + cbw);
            }
            asm volatile("cp.async.commit_group;\n");
            asm volatile("cp.async.wait_group 1;\n");
        } else {
            asm volatile("cp.async.wait_group 0;\n");
        }
        __syncthreads();

        const float* As = Asm + buf * AS_BUF;
        const float* Bs = Bsm + buf * BS_BUF;
#pragma unroll
        for (int ks = 0; ks < 4; ks++) {
            int kk = ks * 8;
            uint32_t af[4][4], bf[4][2];
#pragma unroll
            for (int mt = 0; mt < 4; mt++) {
                int r0 = wm + mt * 16;
                af[mt][0] = __float_as_uint(As[(r0 + gid)     * AS_STRIDE + kk + tig]);
                af[mt][1] = __float_as_uint(As[(r0 + gid + 8) * AS_STRIDE + kk + tig]);
                af[mt][2] = __float_as_uint(As[(r0 + gid)     * AS_STRIDE + kk + tig + 4]);
                af[mt][3] = __float_as_uint(As[(r0 + gid + 8) * AS_STRIDE + kk + tig + 4]);
            }
#pragma unroll
            for (int nt = 0; nt < 4; nt++) {
                int c0 = wn + nt * 8;
                bf[nt][0] = __float_as_uint(Bs[(kk + tig)     * BS_STRIDE + c0 + gid]);
                bf[nt][1] = __float_as_uint(Bs[(kk + tig + 4) * BS_STRIDE + c0 + gid]);
            }
#pragma unroll
            for (int mt = 0; mt < 4; mt++)
#pragma unroll
                for (int nt = 0; nt < 4; nt++)
                    asm volatile(
                        "mma.sync.aligned.m16n8k8.row.col.f32.tf32.tf32.f32 "
                        "{%0,%1,%2,%3}, {%4,%5,%6,%7}, {%8,%9}, {%0,%1,%2,%3};"
                        : "+f"(acc[mt][nt][0]), "+f"(acc[mt][nt][1]),
                          "+f"(acc[mt][nt][2]), "+f"(acc[mt][nt][3])
                        : "r"(af[mt][0]), "r"(af[mt][1]), "r"(af[mt][2]), "r"(af[mt][3]),
                          "r"(bf[nt][0]), "r"(bf[nt][1]));
        }
        __syncthreads();
    }

#pragma unroll
    for (int mt = 0; mt < 4; mt++) {
#pragma unroll
        for (int nt = 0; nt < 4; nt++) {
            int row0 = bm + wm + mt * 16 + gid;
            int row1 = row0 + 8;
            int col  = bn + wn + nt * 8 + tig * 2;
            float2 v0 = make_float2(acc[mt][nt][0], acc[mt][nt][1]);
            float2 v1 = make_float2(acc[mt][nt][2], acc[mt][nt][3]);
            if (CONV) {
                float2 b2 = *(const float2*)(bias + col);
                float2 r0 = *(const float2*)(resid + row0 * 256 + col);
                float2 r1 = *(const float2*)(resid + row1 * 256 + col);
                v0.x = cvt_tf32(fmaxf(v0.x + b2.x + r0.x, 0.f));
                v0.y = cvt_tf32(fmaxf(v0.y + b2.y + r0.y, 0.f));
                v1.x = cvt_tf32(fmaxf(v1.x + b2.x + r1.x, 0.f));
                v1.y = cvt_tf32(fmaxf(v1.y + b2.y + r1.y, 0.f));
            }
            *(float2*)(C + row0 * 256 + col) = v0;
            *(float2*)(C + row1 * 256 + col) = v1;
        }
    }
}

// ---------------- per-node attention scalars ----------------
__global__ void k_scalars(const float* __restrict__ a_s, const float* __restrict__ a_d) {
    int w = (blockIdx.x * 256 + threadIdx.x) >> 5;
    int lane = threadIdx.x & 31;
    if (w >= NTOT) return;
    const float4* r  = (const float4*)g_hw + w * 64;
    const float4* s4 = (const float4*)a_s;
    const float4* d4 = (const float4*)a_d;
    float4 v0 = r[lane], v1 = r[lane + 32];
    float4 sa = s4[lane], sb = s4[lane + 32];
    float4 da = d4[lane], db = d4[lane + 32];
    float ss = v0.x * sa.x + v0.y * sa.y + v0.z * sa.z + v0.w * sa.w
             + v1.x * sb.x + v1.y * sb.y + v1.z * sb.z + v1.w * sb.w;
    float dd = v0.x * da.x + v0.y * da.y + v0.z * da.z + v0.w * da.w
             + v1.x * db.x + v1.y * db.y + v1.z * db.z + v1.w * db.w;
#pragma unroll
    for (int o = 16; o; o >>= 1) {
        ss += __shfl_xor_sync(0xFFFFFFFFu, ss, o);
        dd += __shfl_xor_sync(0xFFFFFFFFu, dd, o);
    }
    if (lane == 0) { g_s[w] = ss; g_d[w] = dd; }
}

// ---------------- edge softmax + aggregate v2 ----------------
// 2 warps per dst node; warp handles 128 contiguous features (1 float4/lane/edge).
// Fast path deg<=96: edge indices + scores live in registers; aggregate loop does
// ONLY hw gathers (weights/indices via shfl), unrolled x4 for MLP.
__global__ __launch_bounds__(256)
void k_gat_edges(const float* __restrict__ bias, int flip) {
    float* hout = flip ? g_h0 : g_h1;
    int gw   = (blockIdx.x * 256 + threadIdx.x) >> 5;   // global warp id
    int lane = threadIdx.x & 31;
    int node = gw >> 1;
    int half = gw & 1;
    if (node >= NTOT) return;
    int beg = g_off[node];
    int cnt = g_off[node + 1] - beg;
    float dj = g_d[node];
    const unsigned FULL = 0xFFFFFFFFu;
    const float4* hw4 = (const float4*)g_hw;
    int foff = half * 32 + lane;                         // float4 index within row

    float4 acc = make_float4(0.f, 0.f, 0.f, 0.f);

    if (cnt <= 96) {
        // ---- load phase: one gather pass, scores into registers ----
        int   sv[3];
        float ev[3];
#pragma unroll
        for (int j = 0; j < 3; j++) {
            int i = lane + j * 32;
            sv[j] = 0; ev[j] = -1e30f;
            if (i < cnt) {
                int s = g_csrc[beg + i];
                sv[j] = s;
                float e = g_s[s] + dj;
                ev[j] = e > 0.f ? e : 0.2f * e;
            }
        }
        float mx = fmaxf(ev[0], fmaxf(ev[1], ev[2]));
#pragma unroll
        for (int o = 16; o; o >>= 1) mx = fmaxf(mx, __shfl_xor_sync(FULL, mx, o));
        float wv[3];
        float sum = 0.f;
#pragma unroll
        for (int j = 0; j < 3; j++) {
            wv[j] = (ev[j] > -1e29f) ? __expf(ev[j] - mx) : 0.f;
            sum += wv[j];
        }
#pragma unroll
        for (int o = 16; o; o >>= 1) sum += __shfl_xor_sync(FULL, sum, o);
        float inv = 1.f / sum;
#pragma unroll
        for (int j = 0; j < 3; j++) wv[j] *= inv;

        // ---- aggregate: slot-major, weights/indices via shfl, unroll x4 ----
#pragma unroll
        for (int slot = 0; slot < 3; slot++) {
            int base = slot * 32;
            int m = cnt - base;
            if (m <= 0) break;
            if (m > 32) m = 32;
            int ssv = sv[slot];
            float swv = wv[slot];
            int j = 0;
            for (; j + 4 <= m; j += 4) {
                int   s0 = __shfl_sync(FULL, ssv, j + 0);
                int   s1 = __shfl_sync(FULL, ssv, j + 1);
                int   s2 = __shfl_sync(FULL, ssv, j + 2);
                int   s3 = __shfl_sync(FULL, ssv, j + 3);
                float w0 = __shfl_sync(FULL, swv, j + 0);
                float w1 = __shfl_sync(FULL, swv, j + 1);
                float w2 = __shfl_sync(FULL, swv, j + 2);
                float w3 = __shfl_sync(FULL, swv, j + 3);
                float4 v0 = hw4[s0 * 64 + foff];
                float4 v1 = hw4[s1 * 64 + foff];
                float4 v2 = hw4[s2 * 64 + foff];
                float4 v3 = hw4[s3 * 64 + foff];
                acc.x += w0 * v0.x + w1 * v1.x + w2 * v2.x + w3 * v3.x;
                acc.y += w0 * v0.y + w1 * v1.y + w2 * v2.y + w3 * v3.y;
                acc.z += w0 * v0.z + w1 * v1.z + w2 * v2.z + w3 * v3.z;
                acc.w += w0 * v0.w + w1 * v1.w + w2 * v2.w + w3 * v3.w;
            }
            for (; j < m; j++) {
                int   s0 = __shfl_sync(FULL, ssv, j);
                float w0 = __shfl_sync(FULL, swv, j);
                float4 v0 = hw4[s0 * 64 + foff];
                acc.x += w0 * v0.x; acc.y += w0 * v0.y;
                acc.z += w0 * v0.z; acc.w += w0 * v0.w;
            }
        }
    } else {
        // ---- fallback (deg > 96): classic 3-pass, warp-uniform ----
        float mx = -1e30f;
        for (int i = lane; i < cnt; i += 32) {
            float e = g_s[g_csrc[beg + i]] + dj;
            e = e > 0.f ? e : 0.2f * e;
            mx = fmaxf(mx, e);
        }
#pragma unroll
        for (int o = 16; o; o >>= 1) mx = fmaxf(mx, __shfl_xor_sync(FULL, mx, o));
        float sum = 0.f;
        for (int i = lane; i < cnt; i += 32) {
            float e = g_s[g_csrc[beg + i]] + dj;
            e = e > 0.f ? e : 0.2f * e;
            sum += __expf(e - mx);
        }
#pragma unroll
        for (int o = 16; o; o >>= 1) sum += __shfl_xor_sync(FULL, sum, o);
        float inv = 1.f / sum;
        for (int i = 0; i < cnt; i++) {
            int s_ = g_csrc[beg + i];
            float e = g_s[s_] + dj;
            e = e > 0.f ? e : 0.2f * e;
            float wt = __expf(e - mx) * inv;
            float4 v = hw4[s_ * 64 + foff];
            acc.x += wt * v.x; acc.y += wt * v.y;
            acc.z += wt * v.z; acc.w += wt * v.w;
        }
    }

    float4 bb = ((const float4*)bias)[foff];
    float4 o;
    o.x = cvt_tf32(fmaxf(acc.x + bb.x, 0.f));
    o.y = cvt_tf32(fmaxf(acc.y + bb.y, 0.f));
    o.z = cvt_tf32(fmaxf(acc.z + bb.z, 0.f));
    o.w = cvt_tf32(fmaxf(acc.w + bb.w, 0.f));
    ((float4*)hout)[node * 64 + foff] = o;
}

// ---------------- final conv (position 0 only) + LayerNorm + relu ----------------
__global__ void k_final(const float* __restrict__ tc_w,
                        const float* __restrict__ tc_b, const float* __restrict__ ln_g,
                        const float* __restrict__ ln_b, float* __restrict__ out) {
    __shared__ float h0s[256], h1s[256], red[256];
    int b = blockIdx.x, t = threadIdx.x;
    h0s[t] = g_h1[(b * NN + 0) * 256 + t];
    h1s[t] = g_h1[(b * NN + 1) * 256 + t];
    __syncthreads();
    float v = tc_b[t];
    const float* wr = tc_w + t * 768;
    for (int c = 0; c < 256; c++)
        v += wr[c * 3 + 1] * h0s[c] + wr[c * 3 + 2] * h1s[c];
    red[t] = v;
    __syncthreads();
    for (int o = 128; o; o >>= 1) { if (t < o) red[t] += red[t + o]; __syncthreads(); }
    float mu = red[0] / 256.f;
    __syncthreads();
    red[t] = (v - mu) * (v - mu);
    __syncthreads();
    for (int o = 128; o; o >>= 1) { if (t < o) red[t] += red[t + o]; __syncthreads(); }
    float var = red[0] / 256.f;
    float rs = rsqrtf(var + 1e-5f);
    out[b * 256 + t] = fmaxf((v - mu) * rs * ln_g[t] + ln_b[t], 0.f);
}

// ---------------- launch ----------------
extern "C" void kernel_launch(void* const* d_in, const int* in_sizes, int n_in,
                              void* d_out, int out_size) {
    (void)in_sizes; (void)n_in; (void)out_size;
    const float* x      = (const float*)d_in[0];
    const int*   ei     = (const int*)d_in[1];
    const float* tc_w   = (const float*)d_in[2];
    const float* tc_b   = (const float*)d_in[3];
    const float* gat_W  = (const float*)d_in[4];
    const float* gat_as = (const float*)d_in[5];
    const float* gat_ad = (const float*)d_in[6];
    const float* gat_b  = (const float*)d_in[7];
    const float* ln_g   = (const float*)d_in[8];
    const float* ln_b   = (const float*)d_in[9];
    float* out = (float*)d_out;

    cudaFuncSetAttribute(k_mma<-1>, cudaFuncAttributeMaxDynamicSharedMemorySize, MMA_SMEM_BYTES);
    cudaFuncSetAttribute(k_mma<0>,  cudaFuncAttributeMaxDynamicSharedMemorySize, MMA_SMEM_BYTES);
    cudaFuncSetAttribute(k_mma<1>,  cudaFuncAttributeMaxDynamicSharedMemorySize, MMA_SMEM_BYTES);
    cudaFuncSetAttribute(k_mma<2>,  cudaFuncAttributeMaxDynamicSharedMemorySize, MMA_SMEM_BYTES);

    // input prep + CSR build
    k_xpad<<<(NB * 4098 * 64 + 255) / 256, 256>>>(x);
    k_wb<<<768, 256>>>(tc_w);
    k_wl<<<LL * 256, 256>>>(gat_W);
    k_deg_init<<<(NTOT + 255) / 256, 256>>>();
    k_deg_count<<<EE / 256, 256>>>(ei);
    k_scan<<<1, 1024>>>();
    k_fill<<<(EP + 255) / 256, 256>>>(ei);

    // temporal conv (as GEMM M=16384, N=256, K=768) + residual + relu -> g_h0
    k_mma<-1><<<dim3(2, 128), 256, MMA_SMEM_BYTES>>>(0, tc_b, x);

    const int EGRID = (NTOT * 2 * 32 + 255) / 256;   // 2 warps per node

    // layer 0: h0 -> hw -> h1
    k_mma<0><<<dim3(2, 128), 256, MMA_SMEM_BYTES>>>(0, nullptr, nullptr);
    k_scalars<<<(NTOT * 32 + 255) / 256, 256>>>(gat_as,       gat_ad);
    k_gat_edges<<<EGRID, 256>>>(gat_b,       0);

    // layer 1: h1 -> hw -> h0
    k_mma<1><<<dim3(2, 128), 256, MMA_SMEM_BYTES>>>(1, nullptr, nullptr);
    k_scalars<<<(NTOT * 32 + 255) / 256, 256>>>(gat_as + 256, gat_ad + 256);
    k_gat_edges<<<EGRID, 256>>>(gat_b + 256, 1);

    // layer 2: h0 -> hw -> h1
    k_mma<2><<<dim3(2, 128), 256, MMA_SMEM_BYTES>>>(0, nullptr, nullptr);
    k_scalars<<<(NTOT * 32 + 255) / 256, 256>>>(gat_as + 512, gat_ad + 512);
    k_gat_edges<<<EGRID, 256>>>(gat_b + 512, 0);

    // final conv at n=0 + layernorm + relu (reads g_h1)
    k_final<<<NB, 256>>>(tc_w, tc_b, ln_g, ln_b, out);
}

// round 9
// speedup vs baseline: 1.0559x; 1.0559x over previous
#include <cuda_runtime.h>
#include <cuda_fp16.h>
#include <cstdint>

#define NB 4
#define NN 4096
#define FF 256
#define HH 256
#define EE 262144
#define NTOT 16384
#define EP (EE + NTOT)
#define LL 3

// ---------------- scratch (static device memory; no allocation) ----------------
__device__ __align__(16) float  g_xpad[NB * (NN + 2) * FF];   // padded x (tf32-rounded)
__device__ __align__(16) float  g_Wb[768 * 256];              // conv weight [K,N] (tf32)
__device__ __align__(16) float  g_Wl[LL * 256 * 256];         // gat_W rounded copies
__device__ __align__(16) float  g_h0[NTOT * HH];
__device__ __align__(16) float  g_h1[NTOT * HH];
__device__ __align__(16) float  g_hw[NTOT * HH];              // fp32 (for k_scalars)
__device__ __align__(16) __half g_hwh[NTOT * HH];             // fp16 mirror (for aggregation)
__device__ float g_s[NTOT];
__device__ float g_d[NTOT];
__device__ int   g_deg[NTOT];
__device__ int   g_off[NTOT + 1];
__device__ int   g_cur[NTOT];
__device__ int   g_csrc[EP];

__device__ __forceinline__ float cvt_tf32(float x) {
    uint32_t u;
    asm("cvt.rna.tf32.f32 %0, %1;" : "=r"(u) : "f"(x));
    return __uint_as_float(u);
}
__device__ __forceinline__ float4 cvt4_tf32(float4 v) {
    return make_float4(cvt_tf32(v.x), cvt_tf32(v.y), cvt_tf32(v.z), cvt_tf32(v.w));
}

// ---------------- fused prep: xpad | wb | wl | deg_init, branched by block range ----------------
#define XPAD_BLOCKS 4098     // NB*4098*64 float4 / 256
#define WB_BLOCKS   768
#define WL_BLOCKS   768
#define DEG_BLOCKS  64
__global__ void k_prep(const float* __restrict__ x, const float* __restrict__ tc_w,
                       const float* __restrict__ gat_W) {
    int b = blockIdx.x;
    if (b < XPAD_BLOCKS) {
        int idx = b * 256 + threadIdx.x;
        if (idx >= NB * 4098 * 64) return;
        int c4 = idx & 63;
        int m  = (idx >> 6) % 4098;
        int bb = idx / (4098 * 64);
        float4 v = make_float4(0.f, 0.f, 0.f, 0.f);
        if (m >= 1 && m <= 4096)
            v = cvt4_tf32(((const float4*)x)[(bb * 4096 + (m - 1)) * 64 + c4]);
        ((float4*)g_xpad)[idx] = v;
    } else if (b < XPAD_BLOCKS + WB_BLOCKS) {
        int idx = (b - XPAD_BLOCKS) * 256 + threadIdx.x;   // 768*256
        int o = idx & 255;
        int r = idx >> 8;
        int c = r & 255;
        int k = r >> 8;
        g_Wb[idx] = cvt_tf32(tc_w[o * 768 + c * 3 + k]);
    } else if (b < XPAD_BLOCKS + WB_BLOCKS + WL_BLOCKS) {
        int idx = (b - XPAD_BLOCKS - WB_BLOCKS) * 256 + threadIdx.x;
        g_Wl[idx] = cvt_tf32(gat_W[idx]);
    } else {
        int i = (b - XPAD_BLOCKS - WB_BLOCKS - WL_BLOCKS) * 256 + threadIdx.x;
        if (i < NTOT) g_deg[i] = 1;                        // self loop
    }
}
#define PREP_BLOCKS (XPAD_BLOCKS + WB_BLOCKS + WL_BLOCKS + DEG_BLOCKS)

// ---------------- CSR build (by dst, self-loops included); edge_index is int32 ----------------
__global__ void k_deg_count(const int* __restrict__ ei) {
    int e = blockIdx.x * 256 + threadIdx.x;
    if (e < EE) atomicAdd(&g_deg[ei[EE + e]], 1);
}
__global__ void k_scan() {
    __shared__ int ssum[1024];
    int t = threadIdx.x;
    int v[16]; int tot = 0;
#pragma unroll
    for (int i = 0; i < 16; i++) { v[i] = g_deg[t * 16 + i]; tot += v[i]; }
    ssum[t] = tot;
    __syncthreads();
    for (int off = 1; off < 1024; off <<= 1) {
        int xv = (t >= off) ? ssum[t - off] : 0;
        __syncthreads();
        ssum[t] += xv;
        __syncthreads();
    }
    int pre = (t == 0) ? 0 : ssum[t - 1];
#pragma unroll
    for (int i = 0; i < 16; i++) {
        g_off[t * 16 + i] = pre;
        g_cur[t * 16 + i] = pre;
        pre += v[i];
    }
    if (t == 1023) g_off[NTOT] = ssum[1023];
}
__global__ void k_fill(const int* __restrict__ ei) {
    int idx = blockIdx.x * 256 + threadIdx.x;
    if (idx < NTOT) {
        int pos = atomicAdd(&g_cur[idx], 1);
        g_csrc[pos] = idx;                                 // self loop
    } else if (idx < NTOT + EE) {
        int e   = idx - NTOT;
        int src = ei[e];
        int dst = ei[EE + e];
        int pos = atomicAdd(&g_cur[dst], 1);
        g_csrc[pos] = src;
    }
}

// ---------------- tf32 MMA GEMM: cp.async 2-stage, 128x128x32, 8 warps ----------------
#define AS_STRIDE 36
#define BS_STRIDE 136
#define AS_BUF (128 * AS_STRIDE)
#define BS_BUF (32 * BS_STRIDE)
#define MMA_SMEM_BYTES ((2 * AS_BUF + 2 * BS_BUF) * 4)   // 71680 B

__device__ __forceinline__ void cp_async16(uint32_t saddr, const void* gptr) {
    asm volatile("cp.async.cg.shared.global [%0], [%1], 16;\n" :: "r"(saddr), "l"(gptr));
}

// LAYER: -1 = conv (A=g_xpad, B=g_Wb, K=768, epilogue); 0..2 = GAT layer
template <int LAYER>
__global__ __launch_bounds__(256, 2)
void k_mma(int flip, const float* __restrict__ bias, const float* __restrict__ resid) {
    constexpr bool CONV = (LAYER < 0);
    const float* A  = CONV ? g_xpad : (flip ? g_h1 : g_h0);
    const float* Bg = CONV ? g_Wb : g_Wl + (LAYER < 0 ? 0 : LAYER) * 65536;
    float* C        = CONV ? g_h0 : g_hw;
    const int T     = CONV ? 24 : 8;

    extern __shared__ __align__(16) float smem[];
    float* Asm = smem;
    float* Bsm = smem + 2 * AS_BUF;
    uint32_t sA = (uint32_t)__cvta_generic_to_shared(Asm);
    uint32_t sB = (uint32_t)__cvta_generic_to_shared(Bsm);

    int tid  = threadIdx.x;
    int wid  = tid >> 5, lane = tid & 31;
    int gid  = lane >> 2, tig = lane & 3;
    int wm   = (wid >> 2) * 64;
    int wn   = (wid & 3) * 32;
    int bm   = blockIdx.y * 128, bn = blockIdx.x * 128;

    int raw = tid >> 3;
    int caw = (tid & 7) * 4;
    int rbw = tid >> 5;
    int cbw = (tid & 31) * 4;

    float acc[4][4][4];
#pragma unroll
    for (int mt = 0; mt < 4; mt++)
#pragma unroll
        for (int nt = 0; nt < 4; nt++)
#pragma unroll
            for (int r = 0; r < 4; r++) acc[mt][nt][r] = 0.f;

#pragma unroll
    for (int i = 0; i < 4; i++) {
        int r = raw + i * 32;
        int row = bm + r;
        const float* ga = A + (CONV ? row * 256 + (row >> 12) * 512 + caw
                                    : row * 256 + caw);
        cp_async16(sA + (r * AS_STRIDE + caw) * 4, ga);
        int rb = rbw + i * 8;
        cp_async16(sB + (rb * BS_STRIDE + cbw) * 4, Bg + rb * 256 + bn + cbw);
    }
    asm volatile("cp.async.commit_group;\n");

    for (int t = 0; t < T; t++) {
        int buf = t & 1;
        if (t + 1 < T) {
            int k0 = (t + 1) * 32;
            uint32_t dA = sA + ((buf ^ 1) * AS_BUF) * 4;
            uint32_t dB = sB + ((buf ^ 1) * BS_BUF) * 4;
#pragma unroll
            for (int i = 0; i < 4; i++) {
                int r = raw + i * 32;
                int row = bm + r;
                const float* ga = A + (CONV ? row * 256 + (row >> 12) * 512 + k0 + caw
                                            : row * 256 + k0 + caw);
                cp_async16(dA + (r * AS_STRIDE + caw) * 4, ga);
                int rb = rbw + i * 8;
                cp_async16(dB + (rb * BS_STRIDE + cbw) * 4, Bg + (k0 + rb) * 256 + bn + cbw);
            }
            asm volatile("cp.async.commit_group;\n");
            asm volatile("cp.async.wait_group 1;\n");
        } else {
            asm volatile("cp.async.wait_group 0;\n");
        }
        __syncthreads();

        const float* As = Asm + buf * AS_BUF;
        const float* Bs = Bsm + buf * BS_BUF;
#pragma unroll
        for (int ks = 0; ks < 4; ks++) {
            int kk = ks * 8;
            uint32_t af[4][4], bf[4][2];
#pragma unroll
            for (int mt = 0; mt < 4; mt++) {
                int r0 = wm + mt * 16;
                af[mt][0] = __float_as_uint(As[(r0 + gid)     * AS_STRIDE + kk + tig]);
                af[mt][1] = __float_as_uint(As[(r0 + gid + 8) * AS_STRIDE + kk + tig]);
                af[mt][2] = __float_as_uint(As[(r0 + gid)     * AS_STRIDE + kk + tig + 4]);
                af[mt][3] = __float_as_uint(As[(r0 + gid + 8) * AS_STRIDE + kk + tig + 4]);
            }
#pragma unroll
            for (int nt = 0; nt < 4; nt++) {
                int c0 = wn + nt * 8;
                bf[nt][0] = __float_as_uint(Bs[(kk + tig)     * BS_STRIDE + c0 + gid]);
                bf[nt][1] = __float_as_uint(Bs[(kk + tig + 4) * BS_STRIDE + c0 + gid]);
            }
#pragma unroll
            for (int mt = 0; mt < 4; mt++)
#pragma unroll
                for (int nt = 0; nt < 4; nt++)
                    asm volatile(
                        "mma.sync.aligned.m16n8k8.row.col.f32.tf32.tf32.f32 "
                        "{%0,%1,%2,%3}, {%4,%5,%6,%7}, {%8,%9}, {%0,%1,%2,%3};"
                        : "+f"(acc[mt][nt][0]), "+f"(acc[mt][nt][1]),
                          "+f"(acc[mt][nt][2]), "+f"(acc[mt][nt][3])
                        : "r"(af[mt][0]), "r"(af[mt][1]), "r"(af[mt][2]), "r"(af[mt][3]),
                          "r"(bf[nt][0]), "r"(bf[nt][1]));
        }
        __syncthreads();
    }

#pragma unroll
    for (int mt = 0; mt < 4; mt++) {
#pragma unroll
        for (int nt = 0; nt < 4; nt++) {
            int row0 = bm + wm + mt * 16 + gid;
            int row1 = row0 + 8;
            int col  = bn + wn + nt * 8 + tig * 2;
            float2 v0 = make_float2(acc[mt][nt][0], acc[mt][nt][1]);
            float2 v1 = make_float2(acc[mt][nt][2], acc[mt][nt][3]);
            if (CONV) {
                float2 b2 = *(const float2*)(bias + col);
                float2 r0 = *(const float2*)(resid + row0 * 256 + col);
                float2 r1 = *(const float2*)(resid + row1 * 256 + col);
                v0.x = cvt_tf32(fmaxf(v0.x + b2.x + r0.x, 0.f));
                v0.y = cvt_tf32(fmaxf(v0.y + b2.y + r0.y, 0.f));
                v1.x = cvt_tf32(fmaxf(v1.x + b2.x + r1.x, 0.f));
                v1.y = cvt_tf32(fmaxf(v1.y + b2.y + r1.y, 0.f));
            } else {
                // fp16 mirror for the aggregation gather (col is even)
                ((__half2*)g_hwh)[(row0 * 256 + col) >> 1] = __float22half2_rn(v0);
                ((__half2*)g_hwh)[(row1 * 256 + col) >> 1] = __float22half2_rn(v1);
            }
            *(float2*)(C + row0 * 256 + col) = v0;
            *(float2*)(C + row1 * 256 + col) = v1;
        }
    }
}

// ---------------- per-node attention scalars (fp32 g_hw) ----------------
__global__ void k_scalars(const float* __restrict__ a_s, const float* __restrict__ a_d) {
    int w = (blockIdx.x * 256 + threadIdx.x) >> 5;
    int lane = threadIdx.x & 31;
    if (w >= NTOT) return;
    const float4* r  = (const float4*)g_hw + w * 64;
    const float4* s4 = (const float4*)a_s;
    const float4* d4 = (const float4*)a_d;
    float4 v0 = r[lane], v1 = r[lane + 32];
    float4 sa = s4[lane], sb = s4[lane + 32];
    float4 da = d4[lane], db = d4[lane + 32];
    float ss = v0.x * sa.x + v0.y * sa.y + v0.z * sa.z + v0.w * sa.w
             + v1.x * sb.x + v1.y * sb.y + v1.z * sb.z + v1.w * sb.w;
    float dd = v0.x * da.x + v0.y * da.y + v0.z * da.z + v0.w * da.w
             + v1.x * db.x + v1.y * db.y + v1.z * db.z + v1.w * db.w;
#pragma unroll
    for (int o = 16; o; o >>= 1) {
        ss += __shfl_xor_sync(0xFFFFFFFFu, ss, o);
        dd += __shfl_xor_sync(0xFFFFFFFFu, dd, o);
    }
    if (lane == 0) { g_s[w] = ss; g_d[w] = dd; }
}

// ---------------- edge softmax + aggregate v3: fp16 gather, 1 warp/node ----------------
// Row = 256 halves = 512 B = 32 lanes x uint4 (8 halves each). fp32 accumulation.
__global__ __launch_bounds__(256)
void k_gat_edges(const float* __restrict__ bias, int flip) {
    float* hout = flip ? g_h0 : g_h1;
    int w = (blockIdx.x * 256 + threadIdx.x) >> 5;
    int lane = threadIdx.x & 31;
    if (w >= NTOT) return;
    int beg = g_off[w];
    int cnt = g_off[w + 1] - beg;
    float dj = g_d[w];
    const unsigned FULL = 0xFFFFFFFFu;
    const uint4* hwh = (const uint4*)g_hwh;            // 32 uint4 per row

    float acc[8];
#pragma unroll
    for (int k = 0; k < 8; k++) acc[k] = 0.f;

#define EDGE_FMA(U, W)                                                     \
    do {                                                                   \
        float2 f0 = __half22float2(((const __half2*)&(U))[0]);             \
        float2 f1 = __half22float2(((const __half2*)&(U))[1]);             \
        float2 f2 = __half22float2(((const __half2*)&(U))[2]);             \
        float2 f3 = __half22float2(((const __half2*)&(U))[3]);             \
        acc[0] += (W) * f0.x; acc[1] += (W) * f0.y;                        \
        acc[2] += (W) * f1.x; acc[3] += (W) * f1.y;                        \
        acc[4] += (W) * f2.x; acc[5] += (W) * f2.y;                        \
        acc[6] += (W) * f3.x; acc[7] += (W) * f3.y;                        \
    } while (0)

    if (cnt <= 96) {
        int   sv[3];
        float ev[3];
#pragma unroll
        for (int j = 0; j < 3; j++) {
            int i = lane + j * 32;
            sv[j] = 0; ev[j] = -1e30f;
            if (i < cnt) {
                int s = g_csrc[beg + i];
                sv[j] = s;
                float e = g_s[s] + dj;
                ev[j] = e > 0.f ? e : 0.2f * e;
            }
        }
        float mx = fmaxf(ev[0], fmaxf(ev[1], ev[2]));
#pragma unroll
        for (int o = 16; o; o >>= 1) mx = fmaxf(mx, __shfl_xor_sync(FULL, mx, o));
        float wv[3];
        float sum = 0.f;
#pragma unroll
        for (int j = 0; j < 3; j++) {
            wv[j] = (ev[j] > -1e29f) ? __expf(ev[j] - mx) : 0.f;
            sum += wv[j];
        }
#pragma unroll
        for (int o = 16; o; o >>= 1) sum += __shfl_xor_sync(FULL, sum, o);
        float inv = 1.f / sum;
#pragma unroll
        for (int j = 0; j < 3; j++) wv[j] *= inv;

#pragma unroll
        for (int slot = 0; slot < 3; slot++) {
            int base = slot * 32;
            int m = cnt - base;
            if (m <= 0) break;
            if (m > 32) m = 32;
            int ssv = sv[slot];
            float swv = wv[slot];
            int j = 0;
            for (; j + 4 <= m; j += 4) {
                int   s0 = __shfl_sync(FULL, ssv, j + 0);
                int   s1 = __shfl_sync(FULL, ssv, j + 1);
                int   s2 = __shfl_sync(FULL, ssv, j + 2);
                int   s3 = __shfl_sync(FULL, ssv, j + 3);
                float w0 = __shfl_sync(FULL, swv, j + 0);
                float w1 = __shfl_sync(FULL, swv, j + 1);
                float w2 = __shfl_sync(FULL, swv, j + 2);
                float w3 = __shfl_sync(FULL, swv, j + 3);
                uint4 u0 = hwh[s0 * 32 + lane];
                uint4 u1 = hwh[s1 * 32 + lane];
                uint4 u2 = hwh[s2 * 32 + lane];
                uint4 u3 = hwh[s3 * 32 + lane];
                EDGE_FMA(u0, w0); EDGE_FMA(u1, w1);
                EDGE_FMA(u2, w2); EDGE_FMA(u3, w3);
            }
            for (; j < m; j++) {
                int   s0 = __shfl_sync(FULL, ssv, j);
                float w0 = __shfl_sync(FULL, swv, j);
                uint4 u0 = hwh[s0 * 32 + lane];
                EDGE_FMA(u0, w0);
            }
        }
    } else {
        // fallback (deg > 96): 3-pass, warp-uniform aggregate
        float mx = -1e30f;
        for (int i = lane; i < cnt; i += 32) {
            float e = g_s[g_csrc[beg + i]] + dj;
            e = e > 0.f ? e : 0.2f * e;
            mx = fmaxf(mx, e);
        }
#pragma unroll
        for (int o = 16; o; o >>= 1) mx = fmaxf(mx, __shfl_xor_sync(FULL, mx, o));
        float sum = 0.f;
        for (int i = lane; i < cnt; i += 32) {
            float e = g_s[g_csrc[beg + i]] + dj;
            e = e > 0.f ? e : 0.2f * e;
            sum += __expf(e - mx);
        }
#pragma unroll
        for (int o = 16; o; o >>= 1) sum += __shfl_xor_sync(FULL, sum, o);
        float inv = 1.f / sum;
        for (int i = 0; i < cnt; i++) {
            int s_ = g_csrc[beg + i];
            float e = g_s[s_] + dj;
            e = e > 0.f ? e : 0.2f * e;
            float wt = __expf(e - mx) * inv;
            uint4 u = hwh[s_ * 32 + lane];
            EDGE_FMA(u, wt);
        }
    }
#undef EDGE_FMA

    // lane owns cols [lane*8, lane*8+8)
    const float4* b4 = (const float4*)bias;
    float4 bb0 = b4[lane * 2], bb1 = b4[lane * 2 + 1];
    float4 o0, o1;
    o0.x = cvt_tf32(fmaxf(acc[0] + bb0.x, 0.f));
    o0.y = cvt_tf32(fmaxf(acc[1] + bb0.y, 0.f));
    o0.z = cvt_tf32(fmaxf(acc[2] + bb0.z, 0.f));
    o0.w = cvt_tf32(fmaxf(acc[3] + bb0.w, 0.f));
    o1.x = cvt_tf32(fmaxf(acc[4] + bb1.x, 0.f));
    o1.y = cvt_tf32(fmaxf(acc[5] + bb1.y, 0.f));
    o1.z = cvt_tf32(fmaxf(acc[6] + bb1.z, 0.f));
    o1.w = cvt_tf32(fmaxf(acc[7] + bb1.w, 0.f));
    ((float4*)hout)[w * 64 + lane * 2]     = o0;
    ((float4*)hout)[w * 64 + lane * 2 + 1] = o1;
}

// ---------------- final conv (position 0 only) + LayerNorm + relu ----------------
__global__ void k_final(const float* __restrict__ tc_w,
                        const float* __restrict__ tc_b, const float* __restrict__ ln_g,
                        const float* __restrict__ ln_b, float* __restrict__ out) {
    __shared__ float h0s[256], h1s[256], red[256];
    int b = blockIdx.x, t = threadIdx.x;
    h0s[t] = g_h1[(b * NN + 0) * 256 + t];
    h1s[t] = g_h1[(b * NN + 1) * 256 + t];
    __syncthreads();
    float v = tc_b[t];
    const float* wr = tc_w + t * 768;
    for (int c = 0; c < 256; c++)
        v += wr[c * 3 + 1] * h0s[c] + wr[c * 3 + 2] * h1s[c];
    red[t] = v;
    __syncthreads();
    for (int o = 128; o; o >>= 1) { if (t < o) red[t] += red[t + o]; __syncthreads(); }
    float mu = red[0] / 256.f;
    __syncthreads();
    red[t] = (v - mu) * (v - mu);
    __syncthreads();
    for (int o = 128; o; o >>= 1) { if (t < o) red[t] += red[t + o]; __syncthreads(); }
    float var = red[0] / 256.f;
    float rs = rsqrtf(var + 1e-5f);
    out[b * 256 + t] = fmaxf((v - mu) * rs * ln_g[t] + ln_b[t], 0.f);
}

// ---------------- launch ----------------
extern "C" void kernel_launch(void* const* d_in, const int* in_sizes, int n_in,
                              void* d_out, int out_size) {
    (void)in_sizes; (void)n_in; (void)out_size;
    const float* x      = (const float*)d_in[0];
    const int*   ei     = (const int*)d_in[1];
    const float* tc_w   = (const float*)d_in[2];
    const float* tc_b   = (const float*)d_in[3];
    const float* gat_W  = (const float*)d_in[4];
    const float* gat_as = (const float*)d_in[5];
    const float* gat_ad = (const float*)d_in[6];
    const float* gat_b  = (const float*)d_in[7];
    const float* ln_g   = (const float*)d_in[8];
    const float* ln_b   = (const float*)d_in[9];
    float* out = (float*)d_out;

    cudaFuncSetAttribute(k_mma<-1>, cudaFuncAttributeMaxDynamicSharedMemorySize, MMA_SMEM_BYTES);
    cudaFuncSetAttribute(k_mma<0>,  cudaFuncAttributeMaxDynamicSharedMemorySize, MMA_SMEM_BYTES);
    cudaFuncSetAttribute(k_mma<1>,  cudaFuncAttributeMaxDynamicSharedMemorySize, MMA_SMEM_BYTES);
    cudaFuncSetAttribute(k_mma<2>,  cudaFuncAttributeMaxDynamicSharedMemorySize, MMA_SMEM_BYTES);

    // launch 1-3: prep + CSR front half (conv placed 4th for the profiler window)
    k_prep<<<PREP_BLOCKS, 256>>>(x, tc_w, gat_W);
    k_deg_count<<<EE / 256, 256>>>(ei);
    k_scan<<<1, 1024>>>();

    // launch 4: temporal conv GEMM (M=16384, N=256, K=768) + residual + relu -> g_h0
    k_mma<-1><<<dim3(2, 128), 256, MMA_SMEM_BYTES>>>(0, tc_b, x);

    // launch 5: CSR scatter (needed only by edges)
    k_fill<<<(EP + 255) / 256, 256>>>(ei);

    const int EGRID = (NTOT * 32 + 255) / 256;   // 1 warp per node

    // layer 0: h0 -> hw -> h1
    k_mma<0><<<dim3(2, 128), 256, MMA_SMEM_BYTES>>>(0, nullptr, nullptr);
    k_scalars<<<EGRID, 256>>>(gat_as,       gat_ad);
    k_gat_edges<<<EGRID, 256>>>(gat_b,       0);

    // layer 1: h1 -> hw -> h0
    k_mma<1><<<dim3(2, 128), 256, MMA_SMEM_BYTES>>>(1, nullptr, nullptr);
    k_scalars<<<EGRID, 256>>>(gat_as + 256, gat_ad + 256);
    k_gat_edges<<<EGRID, 256>>>(gat_b + 256, 1);

    // layer 2: h0 -> hw -> h1
    k_mma<2><<<dim3(2, 128), 256, MMA_SMEM_BYTES>>>(0, nullptr, nullptr);
    k_scalars<<<EGRID, 256>>>(gat_as + 512, gat_ad + 512);
    k_gat_edges<<<EGRID, 256>>>(gat_b + 512, 0);

    // final conv at n=0 + layernorm + relu (reads g_h1)
    k_final<<<NB, 256>>>(tc_w, tc_b, ln_g, ln_b, out);
}

// round 10
// speedup vs baseline: 1.1049x; 1.0464x over previous
#include <cuda_runtime.h>
#include <cuda_fp16.h>
#include <cstdint>

#define NB 4
#define NN 4096
#define FF 256
#define HH 256
#define EE 262144
#define NTOT 16384
#define EP (EE + NTOT)
#define LL 3

// ---------------- scratch (static device memory; no allocation) ----------------
__device__ __align__(16) float  g_xpad[NB * (NN + 2) * FF];   // padded x (tf32-rounded)
__device__ __align__(16) float  g_Wb[768 * 256];              // conv weight [K,N] (tf32)
__device__ __align__(16) float  g_Wl[LL * 256 * 256];         // gat_W rounded copies
__device__ __align__(16) float  g_h0[NTOT * HH];
__device__ __align__(16) float  g_h1[NTOT * HH];
__device__ __align__(16) __half g_hwh[NTOT * HH];             // fp16 hw (aggregation operand)
__device__ float g_s0[NTOT], g_s1[NTOT];                      // per-column-half partial s
__device__ float g_d0[NTOT], g_d1[NTOT];                      // per-column-half partial d
__device__ int   g_deg[NTOT];
__device__ int   g_off[NTOT + 1];
__device__ int   g_cur[NTOT];
__device__ int   g_csrc[EP];

__device__ __forceinline__ float cvt_tf32(float x) {
    uint32_t u;
    asm("cvt.rna.tf32.f32 %0, %1;" : "=r"(u) : "f"(x));
    return __uint_as_float(u);
}
__device__ __forceinline__ float4 cvt4_tf32(float4 v) {
    return make_float4(cvt_tf32(v.x), cvt_tf32(v.y), cvt_tf32(v.z), cvt_tf32(v.w));
}

// ---------------- fused prep: xpad | wb | wl | deg_init ----------------
#define XPAD_BLOCKS 4098
#define WB_BLOCKS   768
#define WL_BLOCKS   768
#define DEG_BLOCKS  64
__global__ void k_prep(const float* __restrict__ x, const float* __restrict__ tc_w,
                       const float* __restrict__ gat_W) {
    int b = blockIdx.x;
    if (b < XPAD_BLOCKS) {
        int idx = b * 256 + threadIdx.x;
        if (idx >= NB * 4098 * 64) return;
        int c4 = idx & 63;
        int m  = (idx >> 6) % 4098;
        int bb = idx / (4098 * 64);
        float4 v = make_float4(0.f, 0.f, 0.f, 0.f);
        if (m >= 1 && m <= 4096)
            v = cvt4_tf32(((const float4*)x)[(bb * 4096 + (m - 1)) * 64 + c4]);
        ((float4*)g_xpad)[idx] = v;
    } else if (b < XPAD_BLOCKS + WB_BLOCKS) {
        int idx = (b - XPAD_BLOCKS) * 256 + threadIdx.x;
        int o = idx & 255;
        int r = idx >> 8;
        int c = r & 255;
        int k = r >> 8;
        g_Wb[idx] = cvt_tf32(tc_w[o * 768 + c * 3 + k]);
    } else if (b < XPAD_BLOCKS + WB_BLOCKS + WL_BLOCKS) {
        int idx = (b - XPAD_BLOCKS - WB_BLOCKS) * 256 + threadIdx.x;
        g_Wl[idx] = cvt_tf32(gat_W[idx]);
    } else {
        int i = (b - XPAD_BLOCKS - WB_BLOCKS - WL_BLOCKS) * 256 + threadIdx.x;
        if (i < NTOT) g_deg[i] = 1;
    }
}
#define PREP_BLOCKS (XPAD_BLOCKS + WB_BLOCKS + WL_BLOCKS + DEG_BLOCKS)

// ---------------- CSR build ----------------
__global__ void k_deg_count(const int* __restrict__ ei) {
    int e = blockIdx.x * 256 + threadIdx.x;
    if (e < EE) atomicAdd(&g_deg[ei[EE + e]], 1);
}
__global__ void k_scan() {
    __shared__ int ssum[1024];
    int t = threadIdx.x;
    int v[16]; int tot = 0;
#pragma unroll
    for (int i = 0; i < 16; i++) { v[i] = g_deg[t * 16 + i]; tot += v[i]; }
    ssum[t] = tot;
    __syncthreads();
    for (int off = 1; off < 1024; off <<= 1) {
        int xv = (t >= off) ? ssum[t - off] : 0;
        __syncthreads();
        ssum[t] += xv;
        __syncthreads();
    }
    int pre = (t == 0) ? 0 : ssum[t - 1];
#pragma unroll
    for (int i = 0; i < 16; i++) {
        g_off[t * 16 + i] = pre;
        g_cur[t * 16 + i] = pre;
        pre += v[i];
    }
    if (t == 1023) g_off[NTOT] = ssum[1023];
}
__global__ void k_fill(const int* __restrict__ ei) {
    int idx = blockIdx.x * 256 + threadIdx.x;
    if (idx < NTOT) {
        int pos = atomicAdd(&g_cur[idx], 1);
        g_csrc[pos] = idx;
    } else if (idx < NTOT + EE) {
        int e   = idx - NTOT;
        int src = ei[e];
        int dst = ei[EE + e];
        int pos = atomicAdd(&g_cur[dst], 1);
        g_csrc[pos] = src;
    }
}

// ---------------- tf32 MMA GEMM: cp.async 3-stage, 128x128x32, 8 warps ----------------
#define AS_STRIDE 36
#define BS_STRIDE 136
#define AS_BUF (128 * AS_STRIDE)
#define BS_BUF (32 * BS_STRIDE)
#define STAGE_BUF (AS_BUF + BS_BUF)                // 8960 floats per stage
#define MMA_SMEM_BYTES (3 * STAGE_BUF * 4)         // 107520 B

__device__ __forceinline__ void cp_async16(uint32_t saddr, const void* gptr) {
    asm volatile("cp.async.cg.shared.global [%0], [%1], 16;\n" :: "r"(saddr), "l"(gptr));
}

// LAYER: -1 = conv (A=g_xpad, B=g_Wb, K=768, bias+resid+relu epilogue -> g_h0 fp32)
// 0..2   = GAT layer: writes g_hwh fp16 + fused s/d partial dot products
//          (aux0 = a_s, aux1 = a_d for that layer)
template <int LAYER>
__global__ __launch_bounds__(256, 2)
void k_mma(int flip, const float* __restrict__ aux0, const float* __restrict__ aux1) {
    constexpr bool CONV = (LAYER < 0);
    const float* A  = CONV ? g_xpad : (flip ? g_h1 : g_h0);
    const float* Bg = CONV ? g_Wb : g_Wl + (LAYER < 0 ? 0 : LAYER) * 65536;
    const int T     = CONV ? 24 : 8;

    extern __shared__ __align__(16) float smem[];
    uint32_t sbase = (uint32_t)__cvta_generic_to_shared(smem);

    int tid  = threadIdx.x;
    int wid  = tid >> 5, lane = tid & 31;
    int gid  = lane >> 2, tig = lane & 3;
    int wm   = (wid >> 2) * 64;
    int wn   = (wid & 3) * 32;
    int bm   = blockIdx.y * 128, bn = blockIdx.x * 128;

    int raw = tid >> 3;
    int caw = (tid & 7) * 4;
    int rbw = tid >> 5;
    int cbw = (tid & 31) * 4;

    float acc[4][4][4];
#pragma unroll
    for (int mt = 0; mt < 4; mt++)
#pragma unroll
        for (int nt = 0; nt < 4; nt++)
#pragma unroll
            for (int r = 0; r < 4; r++) acc[mt][nt][r] = 0.f;

    // stage tile `tt` into stage buffer `sb`
    auto stage = [&](int tt, int sb) {
        int k0 = tt * 32;
        uint32_t dA = sbase + (sb * STAGE_BUF) * 4;
        uint32_t dB = dA + AS_BUF * 4;
#pragma unroll
        for (int i = 0; i < 4; i++) {
            int r = raw + i * 32;
            int row = bm + r;
            const float* ga = A + (CONV ? row * 256 + (row >> 12) * 512 + k0 + caw
                                        : row * 256 + k0 + caw);
            cp_async16(dA + (r * AS_STRIDE + caw) * 4, ga);
            int rb = rbw + i * 8;
            cp_async16(dB + (rb * BS_STRIDE + cbw) * 4, Bg + (k0 + rb) * 256 + bn + cbw);
        }
        asm volatile("cp.async.commit_group;\n");
    };

    stage(0, 0);
    if (T > 1) stage(1, 1);

    for (int t = 0; t < T; t++) {
        int sb = t % 3;
        if (t + 2 < T) {
            stage(t + 2, (t + 2) % 3);
            asm volatile("cp.async.wait_group 2;\n");
        } else if (t + 1 < T) {
            asm volatile("cp.async.wait_group 1;\n");
        } else {
            asm volatile("cp.async.wait_group 0;\n");
        }
        __syncthreads();

        const float* As = smem + sb * STAGE_BUF;
        const float* Bs = As + AS_BUF;
#pragma unroll
        for (int ks = 0; ks < 4; ks++) {
            int kk = ks * 8;
            uint32_t af[4][4], bf[4][2];
#pragma unroll
            for (int mt = 0; mt < 4; mt++) {
                int r0 = wm + mt * 16;
                af[mt][0] = __float_as_uint(As[(r0 + gid)     * AS_STRIDE + kk + tig]);
                af[mt][1] = __float_as_uint(As[(r0 + gid + 8) * AS_STRIDE + kk + tig]);
                af[mt][2] = __float_as_uint(As[(r0 + gid)     * AS_STRIDE + kk + tig + 4]);
                af[mt][3] = __float_as_uint(As[(r0 + gid + 8) * AS_STRIDE + kk + tig + 4]);
            }
#pragma unroll
            for (int nt = 0; nt < 4; nt++) {
                int c0 = wn + nt * 8;
                bf[nt][0] = __float_as_uint(Bs[(kk + tig)     * BS_STRIDE + c0 + gid]);
                bf[nt][1] = __float_as_uint(Bs[(kk + tig + 4) * BS_STRIDE + c0 + gid]);
            }
#pragma unroll
            for (int mt = 0; mt < 4; mt++)
#pragma unroll
                for (int nt = 0; nt < 4; nt++)
                    asm volatile(
                        "mma.sync.aligned.m16n8k8.row.col.f32.tf32.tf32.f32 "
                        "{%0,%1,%2,%3}, {%4,%5,%6,%7}, {%8,%9}, {%0,%1,%2,%3};"
                        : "+f"(acc[mt][nt][0]), "+f"(acc[mt][nt][1]),
                          "+f"(acc[mt][nt][2]), "+f"(acc[mt][nt][3])
                        : "r"(af[mt][0]), "r"(af[mt][1]), "r"(af[mt][2]), "r"(af[mt][3]),
                          "r"(bf[nt][0]), "r"(bf[nt][1]));
        }
        __syncthreads();
    }

    if (CONV) {
        // epilogue: relu(acc + bias + resid) -> g_h0 (tf32-rounded)
        const float* bias  = aux0;
        const float* resid = aux1;
#pragma unroll
        for (int mt = 0; mt < 4; mt++) {
#pragma unroll
            for (int nt = 0; nt < 4; nt++) {
                int row0 = bm + wm + mt * 16 + gid;
                int row1 = row0 + 8;
                int col  = bn + wn + nt * 8 + tig * 2;
                float2 b2 = *(const float2*)(bias + col);
                float2 r0 = *(const float2*)(resid + row0 * 256 + col);
                float2 r1 = *(const float2*)(resid + row1 * 256 + col);
                float2 v0, v1;
                v0.x = cvt_tf32(fmaxf(acc[mt][nt][0] + b2.x + r0.x, 0.f));
                v0.y = cvt_tf32(fmaxf(acc[mt][nt][1] + b2.y + r0.y, 0.f));
                v1.x = cvt_tf32(fmaxf(acc[mt][nt][2] + b2.x + r1.x, 0.f));
                v1.y = cvt_tf32(fmaxf(acc[mt][nt][3] + b2.y + r1.y, 0.f));
                *(float2*)(g_h0 + row0 * 256 + col) = v0;
                *(float2*)(g_h0 + row1 * 256 + col) = v1;
            }
        }
    } else {
        // epilogue: fp16 hw store + fused partial dot products with a_s / a_d
        const float* avs = aux0;   // a_s (layer slice)
        const float* avd = aux1;   // a_d
        float* sS = smem;          // reuse smem (mainloop done, post-sync)
        float* sD = smem + 128;
        if (tid < 128) { sS[tid] = 0.f; sD[tid] = 0.f; }
        __syncthreads();

#pragma unroll
        for (int mt = 0; mt < 4; mt++) {
            float ps0 = 0.f, pd0 = 0.f, ps1 = 0.f, pd1 = 0.f;
#pragma unroll
            for (int nt = 0; nt < 4; nt++) {
                int col = bn + wn + nt * 8 + tig * 2;
                float2 a2s = *(const float2*)(avs + col);
                float2 a2d = *(const float2*)(avd + col);
                ps0 += acc[mt][nt][0] * a2s.x + acc[mt][nt][1] * a2s.y;
                pd0 += acc[mt][nt][0] * a2d.x + acc[mt][nt][1] * a2d.y;
                ps1 += acc[mt][nt][2] * a2s.x + acc[mt][nt][3] * a2s.y;
                pd1 += acc[mt][nt][2] * a2d.x + acc[mt][nt][3] * a2d.y;
                // fp16 store
                int row0 = bm + wm + mt * 16 + gid;
                int row1 = row0 + 8;
                float2 v0 = make_float2(acc[mt][nt][0], acc[mt][nt][1]);
                float2 v1 = make_float2(acc[mt][nt][2], acc[mt][nt][3]);
                ((__half2*)g_hwh)[(row0 * 256 + col) >> 1] = __float22half2_rn(v0);
                ((__half2*)g_hwh)[(row1 * 256 + col) >> 1] = __float22half2_rn(v1);
            }
            // reduce over the quad (tig)
#pragma unroll
            for (int o = 1; o <= 2; o <<= 1) {
                ps0 += __shfl_xor_sync(0xFFFFFFFFu, ps0, o);
                pd0 += __shfl_xor_sync(0xFFFFFFFFu, pd0, o);
                ps1 += __shfl_xor_sync(0xFFFFFFFFu, ps1, o);
                pd1 += __shfl_xor_sync(0xFFFFFFFFu, pd1, o);
            }
            if (tig == 0) {
                int r0 = wm + mt * 16 + gid;
                atomicAdd(&sS[r0],     ps0);
                atomicAdd(&sS[r0 + 8], ps1);
                atomicAdd(&sD[r0],     pd0);
                atomicAdd(&sD[r0 + 8], pd1);
            }
        }
        __syncthreads();
        if (tid < 128) {
            if (blockIdx.x == 0) { g_s0[bm + tid] = sS[tid]; g_d0[bm + tid] = sD[tid]; }
            else                 { g_s1[bm + tid] = sS[tid]; g_d1[bm + tid] = sD[tid]; }
        }
    }
}

// ---------------- edge softmax + aggregate: fp16 gather, 1 warp/node ----------------
__global__ __launch_bounds__(256)
void k_gat_edges(const float* __restrict__ bias, int flip) {
    float* hout = flip ? g_h0 : g_h1;
    int w = (blockIdx.x * 256 + threadIdx.x) >> 5;
    int lane = threadIdx.x & 31;
    if (w >= NTOT) return;
    int beg = g_off[w];
    int cnt = g_off[w + 1] - beg;
    float dj = g_d0[w] + g_d1[w];
    const unsigned FULL = 0xFFFFFFFFu;
    const uint4* hwh = (const uint4*)g_hwh;

    float acc[8];
#pragma unroll
    for (int k = 0; k < 8; k++) acc[k] = 0.f;

#define EDGE_FMA(U, W)                                                     \
    do {                                                                   \
        float2 f0 = __half22float2(((const __half2*)&(U))[0]);             \
        float2 f1 = __half22float2(((const __half2*)&(U))[1]);             \
        float2 f2 = __half22float2(((const __half2*)&(U))[2]);             \
        float2 f3 = __half22float2(((const __half2*)&(U))[3]);             \
        acc[0] += (W) * f0.x; acc[1] += (W) * f0.y;                        \
        acc[2] += (W) * f1.x; acc[3] += (W) * f1.y;                        \
        acc[4] += (W) * f2.x; acc[5] += (W) * f2.y;                        \
        acc[6] += (W) * f3.x; acc[7] += (W) * f3.y;                        \
    } while (0)

    if (cnt <= 96) {
        int   sv[3];
        float ev[3];
#pragma unroll
        for (int j = 0; j < 3; j++) {
            int i = lane + j * 32;
            sv[j] = 0; ev[j] = -1e30f;
            if (i < cnt) {
                int s = g_csrc[beg + i];
                sv[j] = s;
                float e = g_s0[s] + g_s1[s] + dj;
                ev[j] = e > 0.f ? e : 0.2f * e;
            }
        }
        float mx = fmaxf(ev[0], fmaxf(ev[1], ev[2]));
#pragma unroll
        for (int o = 16; o; o >>= 1) mx = fmaxf(mx, __shfl_xor_sync(FULL, mx, o));
        float wv[3];
        float sum = 0.f;
#pragma unroll
        for (int j = 0; j < 3; j++) {
            wv[j] = (ev[j] > -1e29f) ? __expf(ev[j] - mx) : 0.f;
            sum += wv[j];
        }
#pragma unroll
        for (int o = 16; o; o >>= 1) sum += __shfl_xor_sync(FULL, sum, o);
        float inv = 1.f / sum;
#pragma unroll
        for (int j = 0; j < 3; j++) wv[j] *= inv;

#pragma unroll
        for (int slot = 0; slot < 3; slot++) {
            int base = slot * 32;
            int m = cnt - base;
            if (m <= 0) break;
            if (m > 32) m = 32;
            int ssv = sv[slot];
            float swv = wv[slot];
            int j = 0;
            for (; j + 4 <= m; j += 4) {
                int   s0 = __shfl_sync(FULL, ssv, j + 0);
                int   s1 = __shfl_sync(FULL, ssv, j + 1);
                int   s2 = __shfl_sync(FULL, ssv, j + 2);
                int   s3 = __shfl_sync(FULL, ssv, j + 3);
                float w0 = __shfl_sync(FULL, swv, j + 0);
                float w1 = __shfl_sync(FULL, swv, j + 1);
                float w2 = __shfl_sync(FULL, swv, j + 2);
                float w3 = __shfl_sync(FULL, swv, j + 3);
                uint4 u0 = hwh[s0 * 32 + lane];
                uint4 u1 = hwh[s1 * 32 + lane];
                uint4 u2 = hwh[s2 * 32 + lane];
                uint4 u3 = hwh[s3 * 32 + lane];
                EDGE_FMA(u0, w0); EDGE_FMA(u1, w1);
                EDGE_FMA(u2, w2); EDGE_FMA(u3, w3);
            }
            for (; j < m; j++) {
                int   s0 = __shfl_sync(FULL, ssv, j);
                float w0 = __shfl_sync(FULL, swv, j);
                uint4 u0 = hwh[s0 * 32 + lane];
                EDGE_FMA(u0, w0);
            }
        }
    } else {
        float mx = -1e30f;
        for (int i = lane; i < cnt; i += 32) {
            int s = g_csrc[beg + i];
            float e = g_s0[s] + g_s1[s] + dj;
            e = e > 0.f ? e : 0.2f * e;
            mx = fmaxf(mx, e);
        }
#pragma unroll
        for (int o = 16; o; o >>= 1) mx = fmaxf(mx, __shfl_xor_sync(FULL, mx, o));
        float sum = 0.f;
        for (int i = lane; i < cnt; i += 32) {
            int s = g_csrc[beg + i];
            float e = g_s0[s] + g_s1[s] + dj;
            e = e > 0.f ? e : 0.2f * e;
            sum += __expf(e - mx);
        }
#pragma unroll
        for (int o = 16; o; o >>= 1) sum += __shfl_xor_sync(FULL, sum, o);
        float inv = 1.f / sum;
        for (int i = 0; i < cnt; i++) {
            int s_ = g_csrc[beg + i];
            float e = g_s0[s_] + g_s1[s_] + dj;
            e = e > 0.f ? e : 0.2f * e;
            float wt = __expf(e - mx) * inv;
            uint4 u = hwh[s_ * 32 + lane];
            EDGE_FMA(u, wt);
        }
    }
#undef EDGE_FMA

    const float4* b4 = (const float4*)bias;
    float4 bb0 = b4[lane * 2], bb1 = b4[lane * 2 + 1];
    float4 o0, o1;
    o0.x = cvt_tf32(fmaxf(acc[0] + bb0.x, 0.f));
    o0.y = cvt_tf32(fmaxf(acc[1] + bb0.y, 0.f));
    o0.z = cvt_tf32(fmaxf(acc[2] + bb0.z, 0.f));
    o0.w = cvt_tf32(fmaxf(acc[3] + bb0.w, 0.f));
    o1.x = cvt_tf32(fmaxf(acc[4] + bb1.x, 0.f));
    o1.y = cvt_tf32(fmaxf(acc[5] + bb1.y, 0.f));
    o1.z = cvt_tf32(fmaxf(acc[6] + bb1.z, 0.f));
    o1.w = cvt_tf32(fmaxf(acc[7] + bb1.w, 0.f));
    ((float4*)hout)[w * 64 + lane * 2]     = o0;
    ((float4*)hout)[w * 64 + lane * 2 + 1] = o1;
}

// ---------------- final conv (position 0 only) + LayerNorm + relu ----------------
__global__ void k_final(const float* __restrict__ tc_w,
                        const float* __restrict__ tc_b, const float* __restrict__ ln_g,
                        const float* __restrict__ ln_b, float* __restrict__ out) {
    __shared__ float h0s[256], h1s[256], red[256];
    int b = blockIdx.x, t = threadIdx.x;
    h0s[t] = g_h1[(b * NN + 0) * 256 + t];
    h1s[t] = g_h1[(b * NN + 1) * 256 + t];
    __syncthreads();
    float v = tc_b[t];
    const float* wr = tc_w + t * 768;
    for (int c = 0; c < 256; c++)
        v += wr[c * 3 + 1] * h0s[c] + wr[c * 3 + 2] * h1s[c];
    red[t] = v;
    __syncthreads();
    for (int o = 128; o; o >>= 1) { if (t < o) red[t] += red[t + o]; __syncthreads(); }
    float mu = red[0] / 256.f;
    __syncthreads();
    red[t] = (v - mu) * (v - mu);
    __syncthreads();
    for (int o = 128; o; o >>= 1) { if (t < o) red[t] += red[t + o]; __syncthreads(); }
    float var = red[0] / 256.f;
    float rs = rsqrtf(var + 1e-5f);
    out[b * 256 + t] = fmaxf((v - mu) * rs * ln_g[t] + ln_b[t], 0.f);
}

// ---------------- launch ----------------
extern "C" void kernel_launch(void* const* d_in, const int* in_sizes, int n_in,
                              void* d_out, int out_size) {
    (void)in_sizes; (void)n_in; (void)out_size;
    const float* x      = (const float*)d_in[0];
    const int*   ei     = (const int*)d_in[1];
    const float* tc_w   = (const float*)d_in[2];
    const float* tc_b   = (const float*)d_in[3];
    const float* gat_W  = (const float*)d_in[4];
    const float* gat_as = (const float*)d_in[5];
    const float* gat_ad = (const float*)d_in[6];
    const float* gat_b  = (const float*)d_in[7];
    const float* ln_g   = (const float*)d_in[8];
    const float* ln_b   = (const float*)d_in[9];
    float* out = (float*)d_out;

    cudaFuncSetAttribute(k_mma<-1>, cudaFuncAttributeMaxDynamicSharedMemorySize, MMA_SMEM_BYTES);
    cudaFuncSetAttribute(k_mma<0>,  cudaFuncAttributeMaxDynamicSharedMemorySize, MMA_SMEM_BYTES);
    cudaFuncSetAttribute(k_mma<1>,  cudaFuncAttributeMaxDynamicSharedMemorySize, MMA_SMEM_BYTES);
    cudaFuncSetAttribute(k_mma<2>,  cudaFuncAttributeMaxDynamicSharedMemorySize, MMA_SMEM_BYTES);

    // launches 1-3 (conv stays 4th for the profiler window)
    k_prep<<<PREP_BLOCKS, 256>>>(x, tc_w, gat_W);
    k_deg_count<<<EE / 256, 256>>>(ei);
    k_scan<<<1, 1024>>>();

    // launch 4: temporal conv GEMM + residual + relu -> g_h0
    k_mma<-1><<<dim3(2, 128), 256, MMA_SMEM_BYTES>>>(0, tc_b, x);

    // launch 5: CSR scatter
    k_fill<<<(EP + 255) / 256, 256>>>(ei);

    const int EGRID = (NTOT * 32 + 255) / 256;

    // layer 0: h0 -> (hwh, s, d) -> h1
    k_mma<0><<<dim3(2, 128), 256, MMA_SMEM_BYTES>>>(0, gat_as,       gat_ad);
    k_gat_edges<<<EGRID, 256>>>(gat_b,       0);

    // layer 1: h1 -> (hwh, s, d) -> h0
    k_mma<1><<<dim3(2, 128), 256, MMA_SMEM_BYTES>>>(1, gat_as + 256, gat_ad + 256);
    k_gat_edges<<<EGRID, 256>>>(gat_b + 256, 1);

    // layer 2: h0 -> (hwh, s, d) -> h1
    k_mma<2><<<dim3(2, 128), 256, MMA_SMEM_BYTES>>>(0, gat_as + 512, gat_ad + 512);
    k_gat_edges<<<EGRID, 256>>>(gat_b + 512, 0);

    // final conv at n=0 + layernorm + relu (reads g_h1)
    k_final<<<NB, 256>>>(tc_w, tc_b, ln_g, ln_b, out);
}

// round 11
// speedup vs baseline: 1.1367x; 1.0288x over previous
#include <cuda_runtime.h>
#include <cuda_fp16.h>
#include <cstdint>

#define NB 4
#define NN 4096
#define FF 256
#define HH 256
#define EE 262144
#define NTOT 16384
#define EP (EE + NTOT)
#define LL 3

// ---------------- scratch (static device memory; no allocation) ----------------
__device__ __align__(16) float  g_Wb[768 * 256];              // conv weight [K,N] (tf32)
__device__ __align__(16) float  g_Wl[LL * 256 * 256];         // gat_W rounded copies
__device__ __align__(16) float  g_h0[NTOT * HH];
__device__ __align__(16) float  g_h1[NTOT * HH];
__device__ __align__(16) __half g_hwh[NTOT * HH];             // fp16 hw (aggregation operand)
__device__ float g_s0[NTOT], g_s1[NTOT];                      // per-column-half partial s
__device__ float g_d0[NTOT], g_d1[NTOT];                      // per-column-half partial d
__device__ int   g_deg[NTOT];
__device__ int   g_off[NTOT + 1];
__device__ int   g_cur[NTOT];
__device__ int   g_csrc[EP];

__device__ __forceinline__ float cvt_tf32(float x) {
    uint32_t u;
    asm("cvt.rna.tf32.f32 %0, %1;" : "=r"(u) : "f"(x));
    return __uint_as_float(u);
}

// ---------------- fused prep: wb | wl | deg_init ----------------
#define WB_BLOCKS   768
#define WL_BLOCKS   768
#define DEG_BLOCKS  64
__global__ void k_prep(const float* __restrict__ tc_w, const float* __restrict__ gat_W) {
    int b = blockIdx.x;
    if (b < WB_BLOCKS) {
        int idx = b * 256 + threadIdx.x;
        int o = idx & 255;
        int r = idx >> 8;
        int c = r & 255;
        int k = r >> 8;
        g_Wb[idx] = cvt_tf32(tc_w[o * 768 + c * 3 + k]);
    } else if (b < WB_BLOCKS + WL_BLOCKS) {
        int idx = (b - WB_BLOCKS) * 256 + threadIdx.x;
        g_Wl[idx] = cvt_tf32(gat_W[idx]);
    } else {
        int i = (b - WB_BLOCKS - WL_BLOCKS) * 256 + threadIdx.x;
        if (i < NTOT) g_deg[i] = 1;
    }
}
#define PREP_BLOCKS (WB_BLOCKS + WL_BLOCKS + DEG_BLOCKS)

// ---------------- CSR build ----------------
__global__ void k_deg_count(const int* __restrict__ ei) {
    int e = blockIdx.x * 256 + threadIdx.x;
    if (e < EE) atomicAdd(&g_deg[ei[EE + e]], 1);
}
__global__ void k_scan() {
    __shared__ int ssum[1024];
    int t = threadIdx.x;
    int v[16]; int tot = 0;
#pragma unroll
    for (int i = 0; i < 16; i++) { v[i] = g_deg[t * 16 + i]; tot += v[i]; }
    ssum[t] = tot;
    __syncthreads();
    for (int off = 1; off < 1024; off <<= 1) {
        int xv = (t >= off) ? ssum[t - off] : 0;
        __syncthreads();
        ssum[t] += xv;
        __syncthreads();
    }
    int pre = (t == 0) ? 0 : ssum[t - 1];
#pragma unroll
    for (int i = 0; i < 16; i++) {
        g_off[t * 16 + i] = pre;
        g_cur[t * 16 + i] = pre;
        pre += v[i];
    }
    if (t == 1023) g_off[NTOT] = ssum[1023];
}
__global__ void k_fill(const int* __restrict__ ei) {
    int idx = blockIdx.x * 256 + threadIdx.x;
    if (idx < NTOT) {
        int pos = atomicAdd(&g_cur[idx], 1);
        g_csrc[pos] = idx;
    } else if (idx < NTOT + EE) {
        int e   = idx - NTOT;
        int src = ei[e];
        int dst = ei[EE + e];
        int pos = atomicAdd(&g_cur[dst], 1);
        g_csrc[pos] = src;
    }
}

// ---------------- tf32 MMA GEMM: cp.async 3-stage ring, ONE barrier per tile ----------------
#define AS_STRIDE 36
#define BS_STRIDE 136
#define AS_BUF (128 * AS_STRIDE)
#define BS_BUF (32 * BS_STRIDE)
#define STAGE_BUF (AS_BUF + BS_BUF)                // 8960 floats per stage
#define MMA_SMEM_BYTES (3 * STAGE_BUF * 4)         // 107520 B

__device__ __forceinline__ void cp_async16(uint32_t saddr, const void* gptr) {
    asm volatile("cp.async.cg.shared.global [%0], [%1], 16;\n" :: "r"(saddr), "l"(gptr));
}
// ignore-src form: copies src_size bytes (0 or 16), zero-fills the rest
__device__ __forceinline__ void cp_async16_zf(uint32_t saddr, const void* gptr, uint32_t bytes) {
    asm volatile("cp.async.cg.shared.global [%0], [%1], 16, %2;\n"
                 :: "r"(saddr), "l"(gptr), "r"(bytes));
}

// LAYER: -1 = conv (A = x directly with zero-fill halo, B=g_Wb, K=768,
//                   epilogue relu(acc+bias+resid) -> g_h0, aux0=bias, aux1=x)
// 0..2   = GAT layer: fp16 hw store + fused s/d dots (aux0=a_s, aux1=a_d)
template <int LAYER>
__global__ __launch_bounds__(256, 2)
void k_mma(int flip, const float* __restrict__ aux0, const float* __restrict__ aux1) {
    constexpr bool CONV = (LAYER < 0);
    const float* A  = CONV ? aux1 : (flip ? g_h1 : g_h0);   // conv: A = x
    const float* Bg = CONV ? g_Wb : g_Wl + (LAYER < 0 ? 0 : LAYER) * 65536;
    const int T     = CONV ? 24 : 8;

    extern __shared__ __align__(16) float smem[];
    uint32_t sbase = (uint32_t)__cvta_generic_to_shared(smem);

    int tid  = threadIdx.x;
    int wid  = tid >> 5, lane = tid & 31;
    int gid  = lane >> 2, tig = lane & 3;
    int wm   = (wid >> 2) * 64;
    int wn   = (wid & 3) * 32;
    int bm   = blockIdx.y * 128, bn = blockIdx.x * 128;

    int raw = tid >> 3;
    int caw = (tid & 7) * 4;
    int rbw = tid >> 5;
    int cbw = (tid & 31) * 4;

    float acc[4][4][4];
#pragma unroll
    for (int mt = 0; mt < 4; mt++)
#pragma unroll
        for (int nt = 0; nt < 4; nt++)
#pragma unroll
            for (int r = 0; r < 4; r++) acc[mt][nt][r] = 0.f;

    auto stage = [&](int tt, int sb) {
        int k0 = tt * 32;
        uint32_t dA = sbase + (sb * STAGE_BUF) * 4;
        uint32_t dB = dA + AS_BUF * 4;
        if (CONV) {
            // A[row][k] = x[b, m + k/256 - 1, k%256], zero outside [0,4096)
            int tap  = k0 >> 8;                  // entire 32-wide k-tile in one tap
            int colb = (k0 & 255) + caw;
#pragma unroll
            for (int i = 0; i < 4; i++) {
                int r = raw + i * 32;
                int row = bm + r;
                int m = row & 4095;
                int msrc = m + tap - 1;
                uint32_t ok = ((unsigned)msrc < 4096u) ? 16u : 0u;
                int msafe = msrc < 0 ? 0 : (msrc > 4095 ? 4095 : msrc);
                const float* ga = A + (((row >> 12) << 12) + msafe) * 256 + colb;
                cp_async16_zf(dA + (r * AS_STRIDE + caw) * 4, ga, ok);
                int rb = rbw + i * 8;
                cp_async16(dB + (rb * BS_STRIDE + cbw) * 4, Bg + (k0 + rb) * 256 + bn + cbw);
            }
        } else {
#pragma unroll
            for (int i = 0; i < 4; i++) {
                int r = raw + i * 32;
                cp_async16(dA + (r * AS_STRIDE + caw) * 4, A + (bm + r) * 256 + k0 + caw);
                int rb = rbw + i * 8;
                cp_async16(dB + (rb * BS_STRIDE + cbw) * 4, Bg + (k0 + rb) * 256 + bn + cbw);
            }
        }
        asm volatile("cp.async.commit_group;\n");
    };

    stage(0, 0);
    stage(1, 1);

    for (int t = 0; t < T; t++) {
        if (t + 1 < T) asm volatile("cp.async.wait_group 1;\n");
        else           asm volatile("cp.async.wait_group 0;\n");
        __syncthreads();                    // all warps done with compute(t-1)
        if (t + 2 < T) stage(t + 2, (t + 2) % 3);   // overwrites buffer (t-1)%3: safe

        const float* As = smem + (t % 3) * STAGE_BUF;
        const float* Bs = As + AS_BUF;
#pragma unroll
        for (int ks = 0; ks < 4; ks++) {
            int kk = ks * 8;
            uint32_t af[4][4], bf[4][2];
#pragma unroll
            for (int mt = 0; mt < 4; mt++) {
                int r0 = wm + mt * 16;
                af[mt][0] = __float_as_uint(As[(r0 + gid)     * AS_STRIDE + kk + tig]);
                af[mt][1] = __float_as_uint(As[(r0 + gid + 8) * AS_STRIDE + kk + tig]);
                af[mt][2] = __float_as_uint(As[(r0 + gid)     * AS_STRIDE + kk + tig + 4]);
                af[mt][3] = __float_as_uint(As[(r0 + gid + 8) * AS_STRIDE + kk + tig + 4]);
            }
#pragma unroll
            for (int nt = 0; nt < 4; nt++) {
                int c0 = wn + nt * 8;
                bf[nt][0] = __float_as_uint(Bs[(kk + tig)     * BS_STRIDE + c0 + gid]);
                bf[nt][1] = __float_as_uint(Bs[(kk + tig + 4) * BS_STRIDE + c0 + gid]);
            }
#pragma unroll
            for (int mt = 0; mt < 4; mt++)
#pragma unroll
                for (int nt = 0; nt < 4; nt++)
                    asm volatile(
                        "mma.sync.aligned.m16n8k8.row.col.f32.tf32.tf32.f32 "
                        "{%0,%1,%2,%3}, {%4,%5,%6,%7}, {%8,%9}, {%0,%1,%2,%3};"
                        : "+f"(acc[mt][nt][0]), "+f"(acc[mt][nt][1]),
                          "+f"(acc[mt][nt][2]), "+f"(acc[mt][nt][3])
                        : "r"(af[mt][0]), "r"(af[mt][1]), "r"(af[mt][2]), "r"(af[mt][3]),
                          "r"(bf[nt][0]), "r"(bf[nt][1]));
        }
    }

    if (CONV) {
        const float* bias  = aux0;
        const float* resid = aux1;          // resid == x (row-major [16384,256])
#pragma unroll
        for (int mt = 0; mt < 4; mt++) {
#pragma unroll
            for (int nt = 0; nt < 4; nt++) {
                int row0 = bm + wm + mt * 16 + gid;
                int row1 = row0 + 8;
                int col  = bn + wn + nt * 8 + tig * 2;
                float2 b2 = *(const float2*)(bias + col);
                float2 r0 = *(const float2*)(resid + row0 * 256 + col);
                float2 r1 = *(const float2*)(resid + row1 * 256 + col);
                float2 v0, v1;
                v0.x = cvt_tf32(fmaxf(acc[mt][nt][0] + b2.x + r0.x, 0.f));
                v0.y = cvt_tf32(fmaxf(acc[mt][nt][1] + b2.y + r0.y, 0.f));
                v1.x = cvt_tf32(fmaxf(acc[mt][nt][2] + b2.x + r1.x, 0.f));
                v1.y = cvt_tf32(fmaxf(acc[mt][nt][3] + b2.y + r1.y, 0.f));
                *(float2*)(g_h0 + row0 * 256 + col) = v0;
                *(float2*)(g_h0 + row1 * 256 + col) = v1;
            }
        }
    } else {
        // fp16 hw store + fused partial dot products with a_s / a_d
        const float* avs = aux0;
        const float* avd = aux1;
        float* sS = smem;       // buffer-0 region; last compute used buffer (T-1)%3 = 1
        float* sD = smem + 128;
        if (tid < 128) { sS[tid] = 0.f; sD[tid] = 0.f; }
        __syncthreads();

#pragma unroll
        for (int mt = 0; mt < 4; mt++) {
            float ps0 = 0.f, pd0 = 0.f, ps1 = 0.f, pd1 = 0.f;
#pragma unroll
            for (int nt = 0; nt < 4; nt++) {
                int col = bn + wn + nt * 8 + tig * 2;
                float2 a2s = *(const float2*)(avs + col);
                float2 a2d = *(const float2*)(avd + col);
                ps0 += acc[mt][nt][0] * a2s.x + acc[mt][nt][1] * a2s.y;
                pd0 += acc[mt][nt][0] * a2d.x + acc[mt][nt][1] * a2d.y;
                ps1 += acc[mt][nt][2] * a2s.x + acc[mt][nt][3] * a2s.y;
                pd1 += acc[mt][nt][2] * a2d.x + acc[mt][nt][3] * a2d.y;
                int row0 = bm + wm + mt * 16 + gid;
                int row1 = row0 + 8;
                float2 v0 = make_float2(acc[mt][nt][0], acc[mt][nt][1]);
                float2 v1 = make_float2(acc[mt][nt][2], acc[mt][nt][3]);
                ((__half2*)g_hwh)[(row0 * 256 + col) >> 1] = __float22half2_rn(v0);
                ((__half2*)g_hwh)[(row1 * 256 + col) >> 1] = __float22half2_rn(v1);
            }
#pragma unroll
            for (int o = 1; o <= 2; o <<= 1) {
                ps0 += __shfl_xor_sync(0xFFFFFFFFu, ps0, o);
                pd0 += __shfl_xor_sync(0xFFFFFFFFu, pd0, o);
                ps1 += __shfl_xor_sync(0xFFFFFFFFu, ps1, o);
                pd1 += __shfl_xor_sync(0xFFFFFFFFu, pd1, o);
            }
            if (tig == 0) {
                int r0 = wm + mt * 16 + gid;
                atomicAdd(&sS[r0],     ps0);
                atomicAdd(&sS[r0 + 8], ps1);
                atomicAdd(&sD[r0],     pd0);
                atomicAdd(&sD[r0 + 8], pd1);
            }
        }
        __syncthreads();
        if (tid < 128) {
            if (blockIdx.x == 0) { g_s0[bm + tid] = sS[tid]; g_d0[bm + tid] = sD[tid]; }
            else                 { g_s1[bm + tid] = sS[tid]; g_d1[bm + tid] = sD[tid]; }
        }
    }
}

// ---------------- edge softmax + aggregate: fp16 gather, 1 warp/node ----------------
__global__ __launch_bounds__(256)
void k_gat_edges(const float* __restrict__ bias, int flip) {
    float* hout = flip ? g_h0 : g_h1;
    int w = (blockIdx.x * 256 + threadIdx.x) >> 5;
    int lane = threadIdx.x & 31;
    if (w >= NTOT) return;
    int beg = g_off[w];
    int cnt = g_off[w + 1] - beg;
    float dj = g_d0[w] + g_d1[w];
    const unsigned FULL = 0xFFFFFFFFu;
    const uint4* hwh = (const uint4*)g_hwh;

    float acc[8];
#pragma unroll
    for (int k = 0; k < 8; k++) acc[k] = 0.f;

#define EDGE_FMA(U, W)                                                     \
    do {                                                                   \
        float2 f0 = __half22float2(((const __half2*)&(U))[0]);             \
        float2 f1 = __half22float2(((const __half2*)&(U))[1]);             \
        float2 f2 = __half22float2(((const __half2*)&(U))[2]);             \
        float2 f3 = __half22float2(((const __half2*)&(U))[3]);             \
        acc[0] += (W) * f0.x; acc[1] += (W) * f0.y;                        \
        acc[2] += (W) * f1.x; acc[3] += (W) * f1.y;                        \
        acc[4] += (W) * f2.x; acc[5] += (W) * f2.y;                        \
        acc[6] += (W) * f3.x; acc[7] += (W) * f3.y;                        \
    } while (0)

    if (cnt <= 96) {
        int   sv[3];
        float ev[3];
#pragma unroll
        for (int j = 0; j < 3; j++) {
            int i = lane + j * 32;
            sv[j] = 0; ev[j] = -1e30f;
            if (i < cnt) {
                int s = g_csrc[beg + i];
                sv[j] = s;
                float e = g_s0[s] + g_s1[s] + dj;
                ev[j] = e > 0.f ? e : 0.2f * e;
            }
        }
        float mx = fmaxf(ev[0], fmaxf(ev[1], ev[2]));
#pragma unroll
        for (int o = 16; o; o >>= 1) mx = fmaxf(mx, __shfl_xor_sync(FULL, mx, o));
        float wv[3];
        float sum = 0.f;
#pragma unroll
        for (int j = 0; j < 3; j++) {
            wv[j] = (ev[j] > -1e29f) ? __expf(ev[j] - mx) : 0.f;
            sum += wv[j];
        }
#pragma unroll
        for (int o = 16; o; o >>= 1) sum += __shfl_xor_sync(FULL, sum, o);
        float inv = 1.f / sum;
#pragma unroll
        for (int j = 0; j < 3; j++) wv[j] *= inv;

#pragma unroll
        for (int slot = 0; slot < 3; slot++) {
            int base = slot * 32;
            int m = cnt - base;
            if (m <= 0) break;
            if (m > 32) m = 32;
            int ssv = sv[slot];
            float swv = wv[slot];
            int j = 0;
            for (; j + 4 <= m; j += 4) {
                int   s0 = __shfl_sync(FULL, ssv, j + 0);
                int   s1 = __shfl_sync(FULL, ssv, j + 1);
                int   s2 = __shfl_sync(FULL, ssv, j + 2);
                int   s3 = __shfl_sync(FULL, ssv, j + 3);
                float w0 = __shfl_sync(FULL, swv, j + 0);
                float w1 = __shfl_sync(FULL, swv, j + 1);
                float w2 = __shfl_sync(FULL, swv, j + 2);
                float w3 = __shfl_sync(FULL, swv, j + 3);
                uint4 u0 = hwh[s0 * 32 + lane];
                uint4 u1 = hwh[s1 * 32 + lane];
                uint4 u2 = hwh[s2 * 32 + lane];
                uint4 u3 = hwh[s3 * 32 + lane];
                EDGE_FMA(u0, w0); EDGE_FMA(u1, w1);
                EDGE_FMA(u2, w2); EDGE_FMA(u3, w3);
            }
            for (; j < m; j++) {
                int   s0 = __shfl_sync(FULL, ssv, j);
                float w0 = __shfl_sync(FULL, swv, j);
                uint4 u0 = hwh[s0 * 32 + lane];
                EDGE_FMA(u0, w0);
            }
        }
    } else {
        float mx = -1e30f;
        for (int i = lane; i < cnt; i += 32) {
            int s = g_csrc[beg + i];
            float e = g_s0[s] + g_s1[s] + dj;
            e = e > 0.f ? e : 0.2f * e;
            mx = fmaxf(mx, e);
        }
#pragma unroll
        for (int o = 16; o; o >>= 1) mx = fmaxf(mx, __shfl_xor_sync(FULL, mx, o));
        float sum = 0.f;
        for (int i = lane; i < cnt; i += 32) {
            int s = g_csrc[beg + i];
            float e = g_s0[s] + g_s1[s] + dj;
            e = e > 0.f ? e : 0.2f * e;
            sum += __expf(e - mx);
        }
#pragma unroll
        for (int o = 16; o; o >>= 1) sum += __shfl_xor_sync(FULL, sum, o);
        float inv = 1.f / sum;
        for (int i = 0; i < cnt; i++) {
            int s_ = g_csrc[beg + i];
            float e = g_s0[s_] + g_s1[s_] + dj;
            e = e > 0.f ? e : 0.2f * e;
            float wt = __expf(e - mx) * inv;
            uint4 u = hwh[s_ * 32 + lane];
            EDGE_FMA(u, wt);
        }
    }
#undef EDGE_FMA

    const float4* b4 = (const float4*)bias;
    float4 bb0 = b4[lane * 2], bb1 = b4[lane * 2 + 1];
    float4 o0, o1;
    o0.x = cvt_tf32(fmaxf(acc[0] + bb0.x, 0.f));
    o0.y = cvt_tf32(fmaxf(acc[1] + bb0.y, 0.f));
    o0.z = cvt_tf32(fmaxf(acc[2] + bb0.z, 0.f));
    o0.w = cvt_tf32(fmaxf(acc[3] + bb0.w, 0.f));
    o1.x = cvt_tf32(fmaxf(acc[4] + bb1.x, 0.f));
    o1.y = cvt_tf32(fmaxf(acc[5] + bb1.y, 0.f));
    o1.z = cvt_tf32(fmaxf(acc[6] + bb1.z, 0.f));
    o1.w = cvt_tf32(fmaxf(acc[7] + bb1.w, 0.f));
    ((float4*)hout)[w * 64 + lane * 2]     = o0;
    ((float4*)hout)[w * 64 + lane * 2 + 1] = o1;
}

// ---------------- final conv (position 0 only) + LayerNorm + relu ----------------
__global__ void k_final(const float* __restrict__ tc_w,
                        const float* __restrict__ tc_b, const float* __restrict__ ln_g,
                        const float* __restrict__ ln_b, float* __restrict__ out) {
    __shared__ float h0s[256], h1s[256], red[256];
    int b = blockIdx.x, t = threadIdx.x;
    h0s[t] = g_h1[(b * NN + 0) * 256 + t];
    h1s[t] = g_h1[(b * NN + 1) * 256 + t];
    __syncthreads();
    float v = tc_b[t];
    const float* wr = tc_w + t * 768;
    for (int c = 0; c < 256; c++)
        v += wr[c * 3 + 1] * h0s[c] + wr[c * 3 + 2] * h1s[c];
    red[t] = v;
    __syncthreads();
    for (int o = 128; o; o >>= 1) { if (t < o) red[t] += red[t + o]; __syncthreads(); }
    float mu = red[0] / 256.f;
    __syncthreads();
    red[t] = (v - mu) * (v - mu);
    __syncthreads();
    for (int o = 128; o; o >>= 1) { if (t < o) red[t] += red[t + o]; __syncthreads(); }
    float var = red[0] / 256.f;
    float rs = rsqrtf(var + 1e-5f);
    out[b * 256 + t] = fmaxf((v - mu) * rs * ln_g[t] + ln_b[t], 0.f);
}

// ---------------- launch ----------------
extern "C" void kernel_launch(void* const* d_in, const int* in_sizes, int n_in,
                              void* d_out, int out_size) {
    (void)in_sizes; (void)n_in; (void)out_size;
    const float* x      = (const float*)d_in[0];
    const int*   ei     = (const int*)d_in[1];
    const float* tc_w   = (const float*)d_in[2];
    const float* tc_b   = (const float*)d_in[3];
    const float* gat_W  = (const float*)d_in[4];
    const float* gat_as = (const float*)d_in[5];
    const float* gat_ad = (const float*)d_in[6];
    const float* gat_b  = (const float*)d_in[7];
    const float* ln_g   = (const float*)d_in[8];
    const float* ln_b   = (const float*)d_in[9];
    float* out = (float*)d_out;

    cudaFuncSetAttribute(k_mma<-1>, cudaFuncAttributeMaxDynamicSharedMemorySize, MMA_SMEM_BYTES);
    cudaFuncSetAttribute(k_mma<0>,  cudaFuncAttributeMaxDynamicSharedMemorySize, MMA_SMEM_BYTES);
    cudaFuncSetAttribute(k_mma<1>,  cudaFuncAttributeMaxDynamicSharedMemorySize, MMA_SMEM_BYTES);
    cudaFuncSetAttribute(k_mma<2>,  cudaFuncAttributeMaxDynamicSharedMemorySize, MMA_SMEM_BYTES);

    // launches 1-3 (conv stays 4th for the profiler window)
    k_prep<<<PREP_BLOCKS, 256>>>(tc_w, gat_W);
    k_deg_count<<<EE / 256, 256>>>(ei);
    k_scan<<<1, 1024>>>();

    // launch 4: temporal conv GEMM (A = x directly) + residual + relu -> g_h0
    k_mma<-1><<<dim3(2, 128), 256, MMA_SMEM_BYTES>>>(0, tc_b, x);

    // launch 5: CSR scatter
    k_fill<<<(EP + 255) / 256, 256>>>(ei);

    const int EGRID = (NTOT * 32 + 255) / 256;

    // layer 0: h0 -> (hwh, s, d) -> h1
    k_mma<0><<<dim3(2, 128), 256, MMA_SMEM_BYTES>>>(0, gat_as,       gat_ad);
    k_gat_edges<<<EGRID, 256>>>(gat_b,       0);

    // layer 1: h1 -> (hwh, s, d) -> h0
    k_mma<1><<<dim3(2, 128), 256, MMA_SMEM_BYTES>>>(1, gat_as + 256, gat_ad + 256);
    k_gat_edges<<<EGRID, 256>>>(gat_b + 256, 1);

    // layer 2: h0 -> (hwh, s, d) -> h1
    k_mma<2><<<dim3(2, 128), 256, MMA_SMEM_BYTES>>>(0, gat_as + 512, gat_ad + 512);
    k_gat_edges<<<EGRID, 256>>>(gat_b + 512, 0);

    // final conv at n=0 + layernorm + relu (reads g_h1)
    k_final<<<NB, 256>>>(tc_w, tc_b, ln_g, ln_b, out);
}

// round 12
// speedup vs baseline: 1.3739x; 1.2087x over previous
#include <cuda_runtime.h>
#include <cuda_fp16.h>
#include <cstdint>

#define NB 4
#define NN 4096
#define FF 256
#define HH 256
#define EE 262144
#define NTOT 16384
#define EP (EE + NTOT)
#define LL 3

// ---------------- scratch (static device memory; no allocation) ----------------
__device__ __align__(16) __half g_xh[NTOT * 256];             // fp16 copy of x
__device__ __align__(16) __half g_Wb[768 * 256];              // conv weight [K,N] fp16
__device__ __align__(16) __half g_Wl[LL * 256 * 256];         // gat_W fp16
__device__ __align__(16) __half g_h0[NTOT * HH];              // node features fp16
__device__ __align__(16) __half g_h1[NTOT * HH];
__device__ __align__(16) __half g_hwh[NTOT * HH];             // hw fp16 (aggregation operand)
__device__ float g_s0[NTOT], g_s1[NTOT];
__device__ float g_d0[NTOT], g_d1[NTOT];
__device__ int   g_deg[NTOT];
__device__ int   g_off[NTOT + 1];
__device__ int   g_cur[NTOT];
__device__ int   g_csrc[EP];

// ---------------- fused prep: xh | wb | wl | deg_init ----------------
#define XH_BLOCKS   4096     // NTOT*64 float4 / 256
#define WB_BLOCKS   768
#define WL_BLOCKS   768
#define DEG_BLOCKS  64
__global__ void k_prep(const float* __restrict__ x, const float* __restrict__ tc_w,
                       const float* __restrict__ gat_W) {
    int b = blockIdx.x;
    if (b < XH_BLOCKS) {
        int idx = b * 256 + threadIdx.x;              // over NTOT*64 float4s
        float4 v = ((const float4*)x)[idx];
        __half2 h0 = __floats2half2_rn(v.x, v.y);
        __half2 h1 = __floats2half2_rn(v.z, v.w);
        ((__half2*)g_xh)[idx * 2]     = h0;
        ((__half2*)g_xh)[idx * 2 + 1] = h1;
    } else if (b < XH_BLOCKS + WB_BLOCKS) {
        int idx = (b - XH_BLOCKS) * 256 + threadIdx.x;  // 768*256
        int o = idx & 255;
        int r = idx >> 8;
        int c = r & 255;
        int k = r >> 8;
        g_Wb[idx] = __float2half_rn(tc_w[o * 768 + c * 3 + k]);
    } else if (b < XH_BLOCKS + WB_BLOCKS + WL_BLOCKS) {
        int idx = (b - XH_BLOCKS - WB_BLOCKS) * 256 + threadIdx.x;
        g_Wl[idx] = __float2half_rn(gat_W[idx]);
    } else {
        int i = (b - XH_BLOCKS - WB_BLOCKS - WL_BLOCKS) * 256 + threadIdx.x;
        if (i < NTOT) g_deg[i] = 1;
    }
}
#define PREP_BLOCKS (XH_BLOCKS + WB_BLOCKS + WL_BLOCKS + DEG_BLOCKS)

// ---------------- CSR build ----------------
__global__ void k_deg_count(const int* __restrict__ ei) {
    int e = blockIdx.x * 256 + threadIdx.x;
    if (e < EE) atomicAdd(&g_deg[ei[EE + e]], 1);
}
__global__ void k_scan() {
    __shared__ int ssum[1024];
    int t = threadIdx.x;
    int v[16]; int tot = 0;
#pragma unroll
    for (int i = 0; i < 16; i++) { v[i] = g_deg[t * 16 + i]; tot += v[i]; }
    ssum[t] = tot;
    __syncthreads();
    for (int off = 1; off < 1024; off <<= 1) {
        int xv = (t >= off) ? ssum[t - off] : 0;
        __syncthreads();
        ssum[t] += xv;
        __syncthreads();
    }
    int pre = (t == 0) ? 0 : ssum[t - 1];
#pragma unroll
    for (int i = 0; i < 16; i++) {
        g_off[t * 16 + i] = pre;
        g_cur[t * 16 + i] = pre;
        pre += v[i];
    }
    if (t == 1023) g_off[NTOT] = ssum[1023];
}
__global__ void k_fill(const int* __restrict__ ei) {
    int idx = blockIdx.x * 256 + threadIdx.x;
    if (idx < NTOT) {
        int pos = atomicAdd(&g_cur[idx], 1);
        g_csrc[pos] = idx;
    } else if (idx < NTOT + EE) {
        int e   = idx - NTOT;
        int src = ei[e];
        int dst = ei[EE + e];
        int pos = atomicAdd(&g_cur[dst], 1);
        g_csrc[pos] = src;
    }
}

// ---------------- fp16 MMA GEMM: m16n8k16 + ldmatrix, cp.async 3-stage ----------------
// halves; strides multiple of 8 halves (16B) for ldmatrix, conflict-free banks
#define ASH 40                         // 32 + 8 pad halves (80 B/row)
#define BSH 136                        // 128 + 8 pad halves (272 B/row)
#define A_BUF_H (128 * ASH)            // 5120 halves = 10240 B
#define B_BUF_H (32 * BSH)             // 4352 halves = 8704 B
#define STAGE_H (A_BUF_H + B_BUF_H)    // 9472 halves = 18944 B
#define MMA_SMEM_BYTES (3 * STAGE_H * 2)   // 56832 B

__device__ __forceinline__ void cp_async16(uint32_t saddr, const void* gptr) {
    asm volatile("cp.async.cg.shared.global [%0], [%1], 16;\n" :: "r"(saddr), "l"(gptr));
}
__device__ __forceinline__ void cp_async16_zf(uint32_t saddr, const void* gptr, uint32_t bytes) {
    asm volatile("cp.async.cg.shared.global [%0], [%1], 16, %2;\n"
                 :: "r"(saddr), "l"(gptr), "r"(bytes));
}

// LAYER: -1 = conv (A = g_xh with zero-fill halo, B = g_Wb, K=768,
//                   epilogue relu(acc+bias+resid)->g_h0 fp16; aux_b=bias, aux_r=x fp32)
// 0..2   = GAT: fp16 hw store + fused s/d dots (aux_b=a_s, aux_r=a_d)
template <int LAYER>
__global__ __launch_bounds__(256, 2)
void k_mma(int flip, const float* __restrict__ aux_b, const float* __restrict__ aux_r) {
    constexpr bool CONV = (LAYER < 0);
    const __half* A  = CONV ? g_xh : (flip ? g_h1 : g_h0);
    const __half* Bg = CONV ? g_Wb : g_Wl + (LAYER < 0 ? 0 : LAYER) * 65536;
    const int T      = CONV ? 24 : 8;

    extern __shared__ __align__(16) __half smem[];
    uint32_t sbase = (uint32_t)__cvta_generic_to_shared(smem);

    int tid  = threadIdx.x;
    int wid  = tid >> 5, lane = tid & 31;
    int gid  = lane >> 2, tig = lane & 3;
    int wm   = (wid >> 2) * 64;
    int wn   = (wid & 3) * 32;
    int bm   = blockIdx.y * 128, bn = blockIdx.x * 128;

    float acc[4][4][4];
#pragma unroll
    for (int mt = 0; mt < 4; mt++)
#pragma unroll
        for (int nt = 0; nt < 4; nt++)
#pragma unroll
            for (int r = 0; r < 4; r++) acc[mt][nt][r] = 0.f;

    // staging coords: A 512 chunks (row=c>>2, kc=c&3), B 512 chunks (row=c>>4, nc=c&15)
    auto stage = [&](int tt, int sb) {
        int k0 = tt * 32;
        uint32_t dA = sbase + (sb * STAGE_H) * 2;
        uint32_t dB = dA + A_BUF_H * 2;
#pragma unroll
        for (int i = 0; i < 2; i++) {
            int c = tid + i * 256;
            int ra = c >> 2, kc = (c & 3) * 8;
            if (CONV) {
                int row = bm + ra;
                int m = row & 4095;
                int tap = k0 >> 8;
                int msrc = m + tap - 1;
                uint32_t ok = ((unsigned)msrc < 4096u) ? 16u : 0u;
                int msafe = msrc < 0 ? 0 : (msrc > 4095 ? 4095 : msrc);
                const __half* ga = A + (((row >> 12) << 12) + msafe) * 256 + (k0 & 255) + kc;
                cp_async16_zf(dA + (ra * ASH + kc) * 2, ga, ok);
            } else {
                cp_async16(dA + (ra * ASH + kc) * 2, A + (bm + ra) * 256 + k0 + kc);
            }
            int rb = c >> 4, nc = (c & 15) * 8;
            cp_async16(dB + (rb * BSH + nc) * 2, Bg + (k0 + rb) * 256 + bn + nc);
        }
        asm volatile("cp.async.commit_group;\n");
    };

    stage(0, 0);
    stage(1, 1);

    for (int t = 0; t < T; t++) {
        if (t + 1 < T) asm volatile("cp.async.wait_group 1;\n");
        else           asm volatile("cp.async.wait_group 0;\n");
        __syncthreads();                         // all warps done with compute(t-1)
        if (t + 2 < T) stage(t + 2, (t + 2) % 3);

        uint32_t sA = sbase + ((t % 3) * STAGE_H) * 2;
        uint32_t sB = sA + A_BUF_H * 2;
#pragma unroll
        for (int ks = 0; ks < 2; ks++) {         // two 16-wide k-steps per tile
            int kk = ks * 16;
            uint32_t af[4][4], bf[4][2];
#pragma unroll
            for (int mt = 0; mt < 4; mt++) {
                uint32_t addr = sA + (((wm + mt * 16 + (lane & 15)) * ASH) + kk + (lane >> 4) * 8) * 2;
                asm volatile("ldmatrix.sync.aligned.m8n8.x4.shared.b16 {%0,%1,%2,%3}, [%4];"
                             : "=r"(af[mt][0]), "=r"(af[mt][1]), "=r"(af[mt][2]), "=r"(af[mt][3])
                             : "r"(addr));
            }
#pragma unroll
            for (int nt = 0; nt < 4; nt++) {
                uint32_t addr = sB + (((kk + (lane & 15)) * BSH) + wn + nt * 8) * 2;
                asm volatile("ldmatrix.sync.aligned.m8n8.x2.trans.shared.b16 {%0,%1}, [%2];"
                             : "=r"(bf[nt][0]), "=r"(bf[nt][1]) : "r"(addr));
            }
#pragma unroll
            for (int mt = 0; mt < 4; mt++)
#pragma unroll
                for (int nt = 0; nt < 4; nt++)
                    asm volatile(
                        "mma.sync.aligned.m16n8k16.row.col.f32.f16.f16.f32 "
                        "{%0,%1,%2,%3}, {%4,%5,%6,%7}, {%8,%9}, {%0,%1,%2,%3};"
                        : "+f"(acc[mt][nt][0]), "+f"(acc[mt][nt][1]),
                          "+f"(acc[mt][nt][2]), "+f"(acc[mt][nt][3])
                        : "r"(af[mt][0]), "r"(af[mt][1]), "r"(af[mt][2]), "r"(af[mt][3]),
                          "r"(bf[nt][0]), "r"(bf[nt][1]));
        }
    }

    if (CONV) {
        const float* bias  = aux_b;
        const float* resid = aux_r;              // x fp32, row-major [16384,256]
#pragma unroll
        for (int mt = 0; mt < 4; mt++) {
#pragma unroll
            for (int nt = 0; nt < 4; nt++) {
                int row0 = bm + wm + mt * 16 + gid;
                int row1 = row0 + 8;
                int col  = bn + wn + nt * 8 + tig * 2;
                float2 b2 = *(const float2*)(bias + col);
                float2 r0 = *(const float2*)(resid + row0 * 256 + col);
                float2 r1 = *(const float2*)(resid + row1 * 256 + col);
                __half2 v0 = __floats2half2_rn(fmaxf(acc[mt][nt][0] + b2.x + r0.x, 0.f),
                                               fmaxf(acc[mt][nt][1] + b2.y + r0.y, 0.f));
                __half2 v1 = __floats2half2_rn(fmaxf(acc[mt][nt][2] + b2.x + r1.x, 0.f),
                                               fmaxf(acc[mt][nt][3] + b2.y + r1.y, 0.f));
                ((__half2*)g_h0)[(row0 * 256 + col) >> 1] = v0;
                ((__half2*)g_h0)[(row1 * 256 + col) >> 1] = v1;
            }
        }
    } else {
        const float* avs = aux_b;
        const float* avd = aux_r;
        float* sS = (float*)smem;
        float* sD = (float*)smem + 128;
        if (tid < 128) { sS[tid] = 0.f; sD[tid] = 0.f; }
        __syncthreads();

#pragma unroll
        for (int mt = 0; mt < 4; mt++) {
            float ps0 = 0.f, pd0 = 0.f, ps1 = 0.f, pd1 = 0.f;
#pragma unroll
            for (int nt = 0; nt < 4; nt++) {
                int col = bn + wn + nt * 8 + tig * 2;
                float2 a2s = *(const float2*)(avs + col);
                float2 a2d = *(const float2*)(avd + col);
                ps0 += acc[mt][nt][0] * a2s.x + acc[mt][nt][1] * a2s.y;
                pd0 += acc[mt][nt][0] * a2d.x + acc[mt][nt][1] * a2d.y;
                ps1 += acc[mt][nt][2] * a2s.x + acc[mt][nt][3] * a2s.y;
                pd1 += acc[mt][nt][2] * a2d.x + acc[mt][nt][3] * a2d.y;
                int row0 = bm + wm + mt * 16 + gid;
                int row1 = row0 + 8;
                __half2 v0 = __floats2half2_rn(acc[mt][nt][0], acc[mt][nt][1]);
                __half2 v1 = __floats2half2_rn(acc[mt][nt][2], acc[mt][nt][3]);
                ((__half2*)g_hwh)[(row0 * 256 + col) >> 1] = v0;
                ((__half2*)g_hwh)[(row1 * 256 + col) >> 1] = v1;
            }
#pragma unroll
            for (int o = 1; o <= 2; o <<= 1) {
                ps0 += __shfl_xor_sync(0xFFFFFFFFu, ps0, o);
                pd0 += __shfl_xor_sync(0xFFFFFFFFu, pd0, o);
                ps1 += __shfl_xor_sync(0xFFFFFFFFu, ps1, o);
                pd1 += __shfl_xor_sync(0xFFFFFFFFu, pd1, o);
            }
            if (tig == 0) {
                int r0 = wm + mt * 16 + gid;
                atomicAdd(&sS[r0],     ps0);
                atomicAdd(&sS[r0 + 8], ps1);
                atomicAdd(&sD[r0],     pd0);
                atomicAdd(&sD[r0 + 8], pd1);
            }
        }
        __syncthreads();
        if (tid < 128) {
            if (blockIdx.x == 0) { g_s0[bm + tid] = sS[tid]; g_d0[bm + tid] = sD[tid]; }
            else                 { g_s1[bm + tid] = sS[tid]; g_d1[bm + tid] = sD[tid]; }
        }
    }
}

// ---------------- edge softmax + aggregate: fp16 gather, 1 warp/node ----------------
__global__ __launch_bounds__(256)
void k_gat_edges(const float* __restrict__ bias, int flip) {
    __half* hout = flip ? g_h0 : g_h1;
    int w = (blockIdx.x * 256 + threadIdx.x) >> 5;
    int lane = threadIdx.x & 31;
    if (w >= NTOT) return;
    int beg = g_off[w];
    int cnt = g_off[w + 1] - beg;
    float dj = g_d0[w] + g_d1[w];
    const unsigned FULL = 0xFFFFFFFFu;
    const uint4* hwh = (const uint4*)g_hwh;

    float acc[8];
#pragma unroll
    for (int k = 0; k < 8; k++) acc[k] = 0.f;

#define EDGE_FMA(U, W)                                                     \
    do {                                                                   \
        float2 f0 = __half22float2(((const __half2*)&(U))[0]);             \
        float2 f1 = __half22float2(((const __half2*)&(U))[1]);             \
        float2 f2 = __half22float2(((const __half2*)&(U))[2]);             \
        float2 f3 = __half22float2(((const __half2*)&(U))[3]);             \
        acc[0] += (W) * f0.x; acc[1] += (W) * f0.y;                        \
        acc[2] += (W) * f1.x; acc[3] += (W) * f1.y;                        \
        acc[4] += (W) * f2.x; acc[5] += (W) * f2.y;                        \
        acc[6] += (W) * f3.x; acc[7] += (W) * f3.y;                        \
    } while (0)

    if (cnt <= 96) {
        int   sv[3];
        float ev[3];
#pragma unroll
        for (int j = 0; j < 3; j++) {
            int i = lane + j * 32;
            sv[j] = 0; ev[j] = -1e30f;
            if (i < cnt) {
                int s = g_csrc[beg + i];
                sv[j] = s;
                float e = g_s0[s] + g_s1[s] + dj;
                ev[j] = e > 0.f ? e : 0.2f * e;
            }
        }
        float mx = fmaxf(ev[0], fmaxf(ev[1], ev[2]));
#pragma unroll
        for (int o = 16; o; o >>= 1) mx = fmaxf(mx, __shfl_xor_sync(FULL, mx, o));
        float wv[3];
        float sum = 0.f;
#pragma unroll
        for (int j = 0; j < 3; j++) {
            wv[j] = (ev[j] > -1e29f) ? __expf(ev[j] - mx) : 0.f;
            sum += wv[j];
        }
#pragma unroll
        for (int o = 16; o; o >>= 1) sum += __shfl_xor_sync(FULL, sum, o);
        float inv = 1.f / sum;
#pragma unroll
        for (int j = 0; j < 3; j++) wv[j] *= inv;

#pragma unroll
        for (int slot = 0; slot < 3; slot++) {
            int base = slot * 32;
            int m = cnt - base;
            if (m <= 0) break;
            if (m > 32) m = 32;
            int ssv = sv[slot];
            float swv = wv[slot];
            int j = 0;
            for (; j + 4 <= m; j += 4) {
                int   s0 = __shfl_sync(FULL, ssv, j + 0);
                int   s1 = __shfl_sync(FULL, ssv, j + 1);
                int   s2 = __shfl_sync(FULL, ssv, j + 2);
                int   s3 = __shfl_sync(FULL, ssv, j + 3);
                float w0 = __shfl_sync(FULL, swv, j + 0);
                float w1 = __shfl_sync(FULL, swv, j + 1);
                float w2 = __shfl_sync(FULL, swv, j + 2);
                float w3 = __shfl_sync(FULL, swv, j + 3);
                uint4 u0 = hwh[s0 * 32 + lane];
                uint4 u1 = hwh[s1 * 32 + lane];
                uint4 u2 = hwh[s2 * 32 + lane];
                uint4 u3 = hwh[s3 * 32 + lane];
                EDGE_FMA(u0, w0); EDGE_FMA(u1, w1);
                EDGE_FMA(u2, w2); EDGE_FMA(u3, w3);
            }
            for (; j < m; j++) {
                int   s0 = __shfl_sync(FULL, ssv, j);
                float w0 = __shfl_sync(FULL, swv, j);
                uint4 u0 = hwh[s0 * 32 + lane];
                EDGE_FMA(u0, w0);
            }
        }
    } else {
        float mx = -1e30f;
        for (int i = lane; i < cnt; i += 32) {
            int s = g_csrc[beg + i];
            float e = g_s0[s] + g_s1[s] + dj;
            e = e > 0.f ? e : 0.2f * e;
            mx = fmaxf(mx, e);
        }
#pragma unroll
        for (int o = 16; o; o >>= 1) mx = fmaxf(mx, __shfl_xor_sync(FULL, mx, o));
        float sum = 0.f;
        for (int i = lane; i < cnt; i += 32) {
            int s = g_csrc[beg + i];
            float e = g_s0[s] + g_s1[s] + dj;
            e = e > 0.f ? e : 0.2f * e;
            sum += __expf(e - mx);
        }
#pragma unroll
        for (int o = 16; o; o >>= 1) sum += __shfl_xor_sync(FULL, sum, o);
        float inv = 1.f / sum;
        for (int i = 0; i < cnt; i++) {
            int s_ = g_csrc[beg + i];
            float e = g_s0[s_] + g_s1[s_] + dj;
            e = e > 0.f ? e : 0.2f * e;
            float wt = __expf(e - mx) * inv;
            uint4 u = hwh[s_ * 32 + lane];
            EDGE_FMA(u, wt);
        }
    }
#undef EDGE_FMA

    // lane owns halves [lane*8, lane*8+8): relu(acc+bias) -> fp16
    const float4* b4 = (const float4*)bias;
    float4 bb0 = b4[lane * 2], bb1 = b4[lane * 2 + 1];
    uint4 o;
    __half2 p0 = __floats2half2_rn(fmaxf(acc[0] + bb0.x, 0.f), fmaxf(acc[1] + bb0.y, 0.f));
    __half2 p1 = __floats2half2_rn(fmaxf(acc[2] + bb0.z, 0.f), fmaxf(acc[3] + bb0.w, 0.f));
    __half2 p2 = __floats2half2_rn(fmaxf(acc[4] + bb1.x, 0.f), fmaxf(acc[5] + bb1.y, 0.f));
    __half2 p3 = __floats2half2_rn(fmaxf(acc[6] + bb1.z, 0.f), fmaxf(acc[7] + bb1.w, 0.f));
    ((__half2*)&o)[0] = p0; ((__half2*)&o)[1] = p1;
    ((__half2*)&o)[2] = p2; ((__half2*)&o)[3] = p3;
    ((uint4*)hout)[w * 32 + lane] = o;
}

// ---------------- final conv (position 0 only) + LayerNorm + relu ----------------
__global__ void k_final(const float* __restrict__ tc_w,
                        const float* __restrict__ tc_b, const float* __restrict__ ln_g,
                        const float* __restrict__ ln_b, float* __restrict__ out) {
    __shared__ float h0s[256], h1s[256], red[256];
    int b = blockIdx.x, t = threadIdx.x;
    h0s[t] = __half2float(g_h1[(b * NN + 0) * 256 + t]);
    h1s[t] = __half2float(g_h1[(b * NN + 1) * 256 + t]);
    __syncthreads();
    float v = tc_b[t];
    const float* wr = tc_w + t * 768;
    for (int c = 0; c < 256; c++)
        v += wr[c * 3 + 1] * h0s[c] + wr[c * 3 + 2] * h1s[c];
    red[t] = v;
    __syncthreads();
    for (int o = 128; o; o >>= 1) { if (t < o) red[t] += red[t + o]; __syncthreads(); }
    float mu = red[0] / 256.f;
    __syncthreads();
    red[t] = (v - mu) * (v - mu);
    __syncthreads();
    for (int o = 128; o; o >>= 1) { if (t < o) red[t] += red[t + o]; __syncthreads(); }
    float var = red[0] / 256.f;
    float rs = rsqrtf(var + 1e-5f);
    out[b * 256 + t] = fmaxf((v - mu) * rs * ln_g[t] + ln_b[t], 0.f);
}

// ---------------- launch ----------------
extern "C" void kernel_launch(void* const* d_in, const int* in_sizes, int n_in,
                              void* d_out, int out_size) {
    (void)in_sizes; (void)n_in; (void)out_size;
    const float* x      = (const float*)d_in[0];
    const int*   ei     = (const int*)d_in[1];
    const float* tc_w   = (const float*)d_in[2];
    const float* tc_b   = (const float*)d_in[3];
    const float* gat_W  = (const float*)d_in[4];
    const float* gat_as = (const float*)d_in[5];
    const float* gat_ad = (const float*)d_in[6];
    const float* gat_b  = (const float*)d_in[7];
    const float* ln_g   = (const float*)d_in[8];
    const float* ln_b   = (const float*)d_in[9];
    float* out = (float*)d_out;

    cudaFuncSetAttribute(k_mma<-1>, cudaFuncAttributeMaxDynamicSharedMemorySize, MMA_SMEM_BYTES);
    cudaFuncSetAttribute(k_mma<0>,  cudaFuncAttributeMaxDynamicSharedMemorySize, MMA_SMEM_BYTES);
    cudaFuncSetAttribute(k_mma<1>,  cudaFuncAttributeMaxDynamicSharedMemorySize, MMA_SMEM_BYTES);
    cudaFuncSetAttribute(k_mma<2>,  cudaFuncAttributeMaxDynamicSharedMemorySize, MMA_SMEM_BYTES);

    // launches 1-3 (conv stays 4th for the profiler window)
    k_prep<<<PREP_BLOCKS, 256>>>(x, tc_w, gat_W);
    k_deg_count<<<EE / 256, 256>>>(ei);
    k_scan<<<1, 1024>>>();

    // launch 4: temporal conv GEMM (fp16 A from g_xh) + residual + relu -> g_h0
    k_mma<-1><<<dim3(2, 128), 256, MMA_SMEM_BYTES>>>(0, tc_b, x);

    // launch 5: CSR scatter
    k_fill<<<(EP + 255) / 256, 256>>>(ei);

    const int EGRID = (NTOT * 32 + 255) / 256;

    // layer 0: h0 -> (hwh, s, d) -> h1
    k_mma<0><<<dim3(2, 128), 256, MMA_SMEM_BYTES>>>(0, gat_as,       gat_ad);
    k_gat_edges<<<EGRID, 256>>>(gat_b,       0);

    // layer 1: h1 -> (hwh, s, d) -> h0
    k_mma<1><<<dim3(2, 128), 256, MMA_SMEM_BYTES>>>(1, gat_as + 256, gat_ad + 256);
    k_gat_edges<<<EGRID, 256>>>(gat_b + 256, 1);

    // layer 2: h0 -> (hwh, s, d) -> h1
    k_mma<2><<<dim3(2, 128), 256, MMA_SMEM_BYTES>>>(0, gat_as + 512, gat_ad + 512);
    k_gat_edges<<<EGRID, 256>>>(gat_b + 512, 0);

    // final conv at n=0 + layernorm + relu (reads g_h1)
    k_final<<<NB, 256>>>(tc_w, tc_b, ln_g, ln_b, out);
}